// round 4
// baseline (speedup 1.0000x reference)
#include <cuda_runtime.h>
#include <cuda_bf16.h>
#include <cstdint>

// Problem constants (B=1)
#define L 768
#define C_IN 384
#define D 32          // C_OUTER
#define E 128         // C_OUT
#define EPS 1e-5f

// ---------------- scratch (no allocations allowed) ----------------
__device__ float g_right[L * D];
__device__ __align__(16) __nv_bfloat16 g_lh[L * D];   // left hi
__device__ __align__(16) __nv_bfloat16 g_ll[L * D];   // left lo

// ================= PTX helpers =================
__device__ __forceinline__ uint32_t smem_u32(const void* p) {
    uint32_t a;
    asm("{ .reg .u64 t; cvta.to.shared.u64 t, %1; cvt.u32.u64 %0, t; }" : "=r"(a) : "l"(p));
    return a;
}
__device__ __forceinline__ void ldsm_x4(uint32_t* r, uint32_t addr) {
    asm volatile("ldmatrix.sync.aligned.m8n8.x4.shared.b16 {%0,%1,%2,%3}, [%4];"
                 : "=r"(r[0]), "=r"(r[1]), "=r"(r[2]), "=r"(r[3]) : "r"(addr));
}
__device__ __forceinline__ void mma16816(float* c, const uint32_t* a, const uint32_t* b) {
    asm volatile("mma.sync.aligned.m16n8k16.row.col.f32.bf16.bf16.f32 "
                 "{%0,%1,%2,%3}, {%4,%5,%6,%7}, {%8,%9}, {%0,%1,%2,%3};"
                 : "+f"(c[0]), "+f"(c[1]), "+f"(c[2]), "+f"(c[3])
                 : "r"(a[0]), "r"(a[1]), "r"(a[2]), "r"(a[3]), "r"(b[0]), "r"(b[1]));
}

// ---------------- Kernel A: LayerNorm + left/right projections ----------------
__global__ void __launch_bounds__(256) ln_proj_kernel(
    const float* __restrict__ act, const float* __restrict__ mask,
    const float* __restrict__ nw, const float* __restrict__ nb,
    const float* __restrict__ wl, const float* __restrict__ bl,
    const float* __restrict__ wr, const float* __restrict__ br)
{
    __shared__ float s_norm[C_IN];
    __shared__ float warp_sum[8];
    __shared__ float bcast;
    __shared__ float red[256];

    const int l = blockIdx.x;
    const int tid = threadIdx.x;
    const int lane = tid & 31;
    const int wid = tid >> 5;
    const float* arow = act + (size_t)l * C_IN;

    const float x0 = arow[tid];
    const float x1 = (tid < C_IN - 256) ? arow[256 + tid] : 0.0f;

    float s = x0 + x1;
    #pragma unroll
    for (int o = 16; o > 0; o >>= 1) s += __shfl_xor_sync(0xffffffffu, s, o);
    if (lane == 0) warp_sum[wid] = s;
    __syncthreads();
    if (tid == 0) {
        float t = 0.f;
        #pragma unroll
        for (int w = 0; w < 8; ++w) t += warp_sum[w];
        bcast = t * (1.0f / C_IN);
    }
    __syncthreads();
    const float mu = bcast;

    const float d0 = x0 - mu;
    const float d1 = (tid < C_IN - 256) ? (x1 - mu) : 0.0f;
    float v = d0 * d0 + d1 * d1;
    #pragma unroll
    for (int o = 16; o > 0; o >>= 1) v += __shfl_xor_sync(0xffffffffu, v, o);
    if (lane == 0) warp_sum[wid] = v;
    __syncthreads();
    if (tid == 0) {
        float t = 0.f;
        #pragma unroll
        for (int w = 0; w < 8; ++w) t += warp_sum[w];
        bcast = rsqrtf(t * (1.0f / C_IN) + EPS);
    }
    __syncthreads();
    const float rstd = bcast;

    s_norm[tid] = d0 * rstd * nw[tid] + nb[tid];
    if (tid < C_IN - 256)
        s_norm[256 + tid] = d1 * rstd * nw[256 + tid] + nb[256 + tid];
    __syncthreads();

    const int oc  = tid & 63;
    const int q   = tid >> 6;
    const int col = oc & 31;
    const float* w = (oc < 32) ? wl : wr;
    float dot = 0.0f;
    const int c0 = q * (C_IN / 4);
    #pragma unroll 8
    for (int c = c0; c < c0 + C_IN / 4; ++c)
        dot += s_norm[c] * w[c * D + col];
    red[tid] = dot;
    __syncthreads();
    if (tid < 128) red[tid] += red[tid + 128];
    __syncthreads();
    if (tid < 64) {
        const float vv = red[tid] + red[tid + 64];
        const float m = mask[l];
        const float val = m * (vv + ((oc < 32) ? bl[col] : br[col]));
        if (oc < 32) {
            const __nv_bfloat16 h = __float2bfloat16(val);
            g_lh[l * D + col] = h;
            g_ll[l * D + col] = __float2bfloat16(val - __bfloat162float(h));
        } else {
            g_right[l * D + col] = val;
        }
    }
}

// ---------------- Kernel C: mma.sync batched GEMM ----------------
// grid = (2 j-halves, L i), block = 256 (8 warps: 4 m x 2 n)
// A[j,k] = [hiL(32), loL(32), hiL(32)]  bf16, row stride 104 elems (208 B)
// B[e,k] = [hiB(32), hiB(32), loB(32)]  bf16 (col operand, k-major per e)
// out[i,j,e] = sum_k A*B + lin[i,e]
#define RSTRIDE 208            // bytes per A/B row (104 bf16)
#define SOFF_LIN   0
#define SOFF_A     512
#define SOFF_B     (512 + 26624)
#define SOFF_STG   (512 + 2 * 26624)
#define SMEM_PAIR  (512 + 2 * 26624 + 32768)   // 86528

__global__ void __launch_bounds__(256, 2) pair_kernel(
    const float* __restrict__ wo, const float* __restrict__ bo,
    float* __restrict__ out)
{
    extern __shared__ char smem[];
    __shared__ float r_s[D];
    const uint32_t sb = smem_u32(smem);
    const uint32_t sA = sb + SOFF_A;
    const uint32_t sB = sb + SOFF_B;
    const uint32_t sStage = sb + SOFF_STG;
    float* lin_s = reinterpret_cast<float*>(smem + SOFF_LIN);

    const int tid = threadIdx.x;
    const int wid = tid >> 5;
    const int lane = tid & 31;
    const int mw = wid & 3;          // m quarter: rows mw*32
    const int nw = wid >> 2;         // e half: cols nw*64
    const int i = blockIdx.y;
    const int jbase = blockIdx.x * 384;

    if (tid < D) r_s[tid] = g_right[i * D + tid];
    __syncthreads();

    // ---- build B tile (threads 0..127) + lin ----
    if (tid < E) {
        const int e = tid;
        float acc = 0.0f;
        alignas(16) __nv_bfloat16 hi[D], lo[D];
        #pragma unroll
        for (int d = 0; d < D; ++d) {
            const float w1 = wo[d * E + e];
            const float w2 = wo[(D + d) * E + e];
            const float rd = r_s[d];
            const float x = fmaf(rd, w1, w2);
            const __nv_bfloat16 h = __float2bfloat16(x);
            hi[d] = h;
            lo[d] = __float2bfloat16(x - __bfloat162float(h));
            acc = fmaf(rd, w2, acc);
        }
        lin_s[e] = bo[e] - acc;
        const uint4* h4 = reinterpret_cast<const uint4*>(hi);
        const uint4* l4 = reinterpret_cast<const uint4*>(lo);
        char* rowp = smem + SOFF_B + e * RSTRIDE;
        #pragma unroll
        for (int c = 0; c < 4; ++c) {
            *reinterpret_cast<uint4*>(rowp + c * 16)        = h4[c];
            *reinterpret_cast<uint4*>(rowp + 64 + c * 16)   = h4[c];
            *reinterpret_cast<uint4*>(rowp + 128 + c * 16)  = l4[c];
        }
    }

    const uint4* lh4 = reinterpret_cast<const uint4*>(g_lh);
    const uint4* ll4 = reinterpret_cast<const uint4*>(g_ll);

    for (int jt = 0; jt < 3; ++jt) {
        const int j0 = jbase + jt * 128;

        // ---- build A tile: 128 rows x 12 16B-chunks ----
        #pragma unroll
        for (int idx = tid; idx < 2048; idx += 256) {
            const int c = idx & 15;
            if (c >= 12) continue;
            const int row = idx >> 4;
            const uint4 v = (c < 4) ? lh4[(j0 + row) * 4 + c]
                          : (c < 8) ? ll4[(j0 + row) * 4 + (c - 4)]
                                    : lh4[(j0 + row) * 4 + (c - 8)];
            *reinterpret_cast<uint4*>(smem + SOFF_A + row * RSTRIDE + c * 16) = v;
        }
        __syncthreads();

        // ---- mainloop: 6 k-tiles of 16 ----
        float acc[2][8][4];
        #pragma unroll
        for (int m = 0; m < 2; ++m)
            #pragma unroll
            for (int n = 0; n < 8; ++n)
                #pragma unroll
                for (int q = 0; q < 4; ++q) acc[m][n][q] = 0.0f;

        #pragma unroll
        for (int kt = 0; kt < 6; ++kt) {
            const uint32_t kb = kt * 32;
            uint32_t bfr[8][2];
            #pragma unroll
            for (int p = 0; p < 4; ++p) {
                const uint32_t er = nw * 64 + p * 16;
                const uint32_t row = er + (lane & 7) + ((lane >> 4) << 3);
                const uint32_t addr = sB + row * RSTRIDE + kb + (((lane >> 3) & 1) << 4);
                uint32_t r[4];
                ldsm_x4(r, addr);
                bfr[2 * p][0] = r[0]; bfr[2 * p][1] = r[1];
                bfr[2 * p + 1][0] = r[2]; bfr[2 * p + 1][1] = r[3];
            }
            #pragma unroll
            for (int m = 0; m < 2; ++m) {
                const uint32_t jr = mw * 32 + m * 16 + (lane & 15);
                const uint32_t addr = sA + jr * RSTRIDE + kb + ((lane >> 4) << 4);
                uint32_t a[4];
                ldsm_x4(a, addr);
                #pragma unroll
                for (int n = 0; n < 8; ++n)
                    mma16816(acc[m][n], a, bfr[n]);
            }
        }
        __syncthreads();

        // ---- epilogue: two 64-row passes through swizzled stage ----
        #pragma unroll
        for (int P = 0; P < 2; ++P) {
            if ((mw >> 1) == P) {
                #pragma unroll
                for (int m = 0; m < 2; ++m) {
                    const uint32_t rr0 = (mw & 1) * 32 + m * 16 + (lane >> 2);
                    #pragma unroll
                    for (int n = 0; n < 8; ++n) {
                        const uint32_t ec = nw * 64 + n * 8 + 2 * (lane & 3);
                        const uint32_t chunk = ec >> 2;
                        const uint32_t off = (ec & 2) << 2;
                        const uint32_t a0 = sStage + rr0 * 512 + ((chunk ^ (rr0 & 7)) << 4) + off;
                        const uint32_t rr1 = rr0 + 8;
                        const uint32_t a1 = sStage + rr1 * 512 + ((chunk ^ (rr1 & 7)) << 4) + off;
                        asm volatile("st.shared.v2.f32 [%0], {%1,%2};"
                                     :: "r"(a0), "f"(acc[m][n][0]), "f"(acc[m][n][1]) : "memory");
                        asm volatile("st.shared.v2.f32 [%0], {%1,%2};"
                                     :: "r"(a1), "f"(acc[m][n][2]), "f"(acc[m][n][3]) : "memory");
                    }
                }
            }
            __syncthreads();
            const float4 lv = reinterpret_cast<const float4*>(lin_s)[lane];
            #pragma unroll
            for (int it = 0; it < 8; ++it) {
                const int r2 = wid + it * 8;
                const uint32_t la = sStage + r2 * 512 + (((uint32_t)(lane ^ (r2 & 7))) << 4);
                float v0, v1, v2, v3;
                asm volatile("ld.shared.v4.f32 {%0,%1,%2,%3}, [%4];"
                             : "=f"(v0), "=f"(v1), "=f"(v2), "=f"(v3) : "r"(la));
                float4 v;
                v.x = v0 + lv.x; v.y = v1 + lv.y; v.z = v2 + lv.z; v.w = v3 + lv.w;
                *reinterpret_cast<float4*>(out + ((size_t)i * L + j0 + P * 64 + r2) * E + lane * 4) = v;
            }
            __syncthreads();
        }
    }
}

// ---------------- launch ----------------
extern "C" void kernel_launch(void* const* d_in, const int* in_sizes, int n_in,
                              void* d_out, int out_size)
{
    const float* act  = (const float*)d_in[0];
    const float* mask = (const float*)d_in[1];
    const float* nw   = (const float*)d_in[2];
    const float* nb   = (const float*)d_in[3];
    const float* wl   = (const float*)d_in[4];
    const float* bl   = (const float*)d_in[5];
    const float* wr   = (const float*)d_in[6];
    const float* br   = (const float*)d_in[7];
    const float* wo   = (const float*)d_in[8];
    const float* bo   = (const float*)d_in[9];
    float* out = (float*)d_out;

    cudaFuncSetAttribute(pair_kernel, cudaFuncAttributeMaxDynamicSharedMemorySize, SMEM_PAIR);

    ln_proj_kernel<<<L, 256>>>(act, mask, nw, nb, wl, bl, wr, br);
    pair_kernel<<<dim3(2, L), 256, SMEM_PAIR>>>(wo, bo, out);
}

// round 5
// speedup vs baseline: 1.3371x; 1.3371x over previous
#include <cuda_runtime.h>
#include <cuda_fp16.h>
#include <cstdint>

// Problem constants (B=1)
#define L 768
#define C_IN 384
#define D 32          // C_OUTER
#define E 128         // C_OUT
#define EPS 1e-5f

// ---------------- scratch (no allocations allowed) ----------------
__device__ float g_right[L * D];
__device__ __align__(16) __half g_lh[L * D];   // left hi (fp16)
__device__ __align__(16) __half g_ll[L * D];   // left lo (fp16)

// ================= PTX helpers =================
__device__ __forceinline__ uint32_t smem_u32(const void* p) {
    uint32_t a;
    asm("{ .reg .u64 t; cvta.to.shared.u64 t, %1; cvt.u32.u64 %0, t; }" : "=r"(a) : "l"(p));
    return a;
}
__device__ __forceinline__ void ldsm_x4(uint32_t* r, uint32_t addr) {
    asm volatile("ldmatrix.sync.aligned.m8n8.x4.shared.b16 {%0,%1,%2,%3}, [%4];"
                 : "=r"(r[0]), "=r"(r[1]), "=r"(r[2]), "=r"(r[3]) : "r"(addr));
}
__device__ __forceinline__ void mma16816(float* c, const uint32_t* a, const uint32_t* b) {
    asm volatile("mma.sync.aligned.m16n8k16.row.col.f32.f16.f16.f32 "
                 "{%0,%1,%2,%3}, {%4,%5,%6,%7}, {%8,%9}, {%0,%1,%2,%3};"
                 : "+f"(c[0]), "+f"(c[1]), "+f"(c[2]), "+f"(c[3])
                 : "r"(a[0]), "r"(a[1]), "r"(a[2]), "r"(a[3]), "r"(b[0]), "r"(b[1]));
}

// ---------------- Kernel A: LayerNorm + left/right projections ----------------
__global__ void __launch_bounds__(256) ln_proj_kernel(
    const float* __restrict__ act, const float* __restrict__ mask,
    const float* __restrict__ nw, const float* __restrict__ nb,
    const float* __restrict__ wl, const float* __restrict__ bl,
    const float* __restrict__ wr, const float* __restrict__ br)
{
    __shared__ float s_norm[C_IN];
    __shared__ float warp_sum[8];
    __shared__ float bcast;
    __shared__ float red[256];

    const int l = blockIdx.x;
    const int tid = threadIdx.x;
    const int lane = tid & 31;
    const int wid = tid >> 5;
    const float* arow = act + (size_t)l * C_IN;

    const float x0 = arow[tid];
    const float x1 = (tid < C_IN - 256) ? arow[256 + tid] : 0.0f;

    float s = x0 + x1;
    #pragma unroll
    for (int o = 16; o > 0; o >>= 1) s += __shfl_xor_sync(0xffffffffu, s, o);
    if (lane == 0) warp_sum[wid] = s;
    __syncthreads();
    if (tid == 0) {
        float t = 0.f;
        #pragma unroll
        for (int w = 0; w < 8; ++w) t += warp_sum[w];
        bcast = t * (1.0f / C_IN);
    }
    __syncthreads();
    const float mu = bcast;

    const float d0 = x0 - mu;
    const float d1 = (tid < C_IN - 256) ? (x1 - mu) : 0.0f;
    float v = d0 * d0 + d1 * d1;
    #pragma unroll
    for (int o = 16; o > 0; o >>= 1) v += __shfl_xor_sync(0xffffffffu, v, o);
    if (lane == 0) warp_sum[wid] = v;
    __syncthreads();
    if (tid == 0) {
        float t = 0.f;
        #pragma unroll
        for (int w = 0; w < 8; ++w) t += warp_sum[w];
        bcast = rsqrtf(t * (1.0f / C_IN) + EPS);
    }
    __syncthreads();
    const float rstd = bcast;

    s_norm[tid] = d0 * rstd * nw[tid] + nb[tid];
    if (tid < C_IN - 256)
        s_norm[256 + tid] = d1 * rstd * nw[256 + tid] + nb[256 + tid];
    __syncthreads();

    const int oc  = tid & 63;
    const int q   = tid >> 6;
    const int col = oc & 31;
    const float* w = (oc < 32) ? wl : wr;
    float dot = 0.0f;
    const int c0 = q * (C_IN / 4);
    #pragma unroll 8
    for (int c = c0; c < c0 + C_IN / 4; ++c)
        dot += s_norm[c] * w[c * D + col];
    red[tid] = dot;
    __syncthreads();
    if (tid < 128) red[tid] += red[tid + 128];
    __syncthreads();
    if (tid < 64) {
        const float vv = red[tid] + red[tid + 64];
        const float m = mask[l];
        const float val = m * (vv + ((oc < 32) ? bl[col] : br[col]));
        if (oc < 32) {
            const __half h = __float2half_rn(val);
            g_lh[l * D + col] = h;
            g_ll[l * D + col] = __float2half_rn(val - __half2float(h));
        } else {
            g_right[l * D + col] = val;
        }
    }
}

// ---------------- Kernel C: mma.sync batched GEMM (fp16 2-term, K=64) ----------------
// grid = (2 j-halves, L i), block = 256 (8 warps: 4 mw x 2 nw)
// A[j,k] = [hiL(32), loL(32)] fp16, row stride 144 B
// B[e,k] = [hiB(32), hiB(32)] fp16
// out[i,j,e] = A.B + lin[i,e]
#define RSTRIDE 144
#define SOFF_LIN   0
#define SOFF_A     512
#define SOFF_B     (512 + 18432)
#define SOFF_STG   (512 + 2 * 18432)
#define SMEM_PAIR  (512 + 2 * 18432 + 32768)   // 70144

__global__ void __launch_bounds__(256, 2) pair_kernel(
    const float* __restrict__ wo, const float* __restrict__ bo,
    float* __restrict__ out)
{
    extern __shared__ char smem[];
    __shared__ float r_s[D];
    const uint32_t sb = smem_u32(smem);
    const uint32_t sA = sb + SOFF_A;
    const uint32_t sB = sb + SOFF_B;
    const uint32_t sStage = sb + SOFF_STG;
    float* lin_s = reinterpret_cast<float*>(smem + SOFF_LIN);

    const int tid = threadIdx.x;
    const int wid = tid >> 5;
    const int lane = tid & 31;
    const int mw = wid & 3;          // m sub-row: 16 rows
    const int nw = wid >> 2;         // e half: cols nw*64
    const int i = blockIdx.y;
    const int jbase = blockIdx.x * 384;

    if (tid < D) r_s[tid] = g_right[i * D + tid];
    __syncthreads();

    // ---- build B tile (threads 0..127) + lin ----
    if (tid < E) {
        const int e = tid;
        float acc = 0.0f;
        alignas(16) __half hi[D];
        #pragma unroll
        for (int d = 0; d < D; ++d) {
            const float w1 = wo[d * E + e];
            const float w2 = wo[(D + d) * E + e];
            const float rd = r_s[d];
            const float x = fmaf(rd, w1, w2);
            hi[d] = __float2half_rn(x);
            acc = fmaf(rd, w2, acc);
        }
        lin_s[e] = bo[e] - acc;
        const uint4* h4 = reinterpret_cast<const uint4*>(hi);
        char* rowp = smem + SOFF_B + e * RSTRIDE;
        #pragma unroll
        for (int c = 0; c < 4; ++c) {
            *reinterpret_cast<uint4*>(rowp + c * 16)       = h4[c];
            *reinterpret_cast<uint4*>(rowp + 64 + c * 16)  = h4[c];
        }
    }

    const uint4* lh4 = reinterpret_cast<const uint4*>(g_lh);
    const uint4* ll4 = reinterpret_cast<const uint4*>(g_ll);

    // ---- build first A tile: 128 rows x 8 16B-chunks ----
    {
        const int j0 = jbase;
        #pragma unroll
        for (int q = 0; q < 4; ++q) {
            const int idx = tid + q * 256;
            const int c = idx & 7;
            const int row = idx >> 3;
            const uint4 v = (c < 4) ? lh4[(j0 + row) * 4 + c]
                                    : ll4[(j0 + row) * 4 + (c - 4)];
            *reinterpret_cast<uint4*>(smem + SOFF_A + row * RSTRIDE + c * 16) = v;
        }
    }
    __syncthreads();

    for (int jt = 0; jt < 3; ++jt) {
        const int j0 = jbase + jt * 128;

        // ---- mainloop: 4 k-tiles of 16 ----
        float acc[2][8][4];
        #pragma unroll
        for (int m = 0; m < 2; ++m)
            #pragma unroll
            for (int n = 0; n < 8; ++n)
                #pragma unroll
                for (int q = 0; q < 4; ++q) acc[m][n][q] = 0.0f;

        #pragma unroll
        for (int kt = 0; kt < 4; ++kt) {
            const uint32_t kb = kt * 32;
            uint32_t bfr[8][2];
            #pragma unroll
            for (int p = 0; p < 4; ++p) {
                const uint32_t er = nw * 64 + p * 16;
                const uint32_t row = er + (lane & 7) + ((lane >> 4) << 3);
                const uint32_t addr = sB + row * RSTRIDE + kb + (((lane >> 3) & 1) << 4);
                uint32_t r[4];
                ldsm_x4(r, addr);
                bfr[2 * p][0] = r[0]; bfr[2 * p][1] = r[1];
                bfr[2 * p + 1][0] = r[2]; bfr[2 * p + 1][1] = r[3];
            }
            #pragma unroll
            for (int m = 0; m < 2; ++m) {
                const uint32_t jr = m * 64 + mw * 16 + (lane & 15);
                const uint32_t addr = sA + jr * RSTRIDE + kb + ((lane >> 4) << 4);
                uint32_t a[4];
                ldsm_x4(a, addr);
                #pragma unroll
                for (int n = 0; n < 8; ++n)
                    mma16816(acc[m][n], a, bfr[n]);
            }
        }

        // ---- prefetch next A tile (global loads issued early) ----
        uint4 pf[4];
        const bool has_next = (jt < 2);
        if (has_next) {
            const int j1 = j0 + 128;
            #pragma unroll
            for (int q = 0; q < 4; ++q) {
                const int idx = tid + q * 256;
                const int c = idx & 7;
                const int row = idx >> 3;
                pf[q] = (c < 4) ? lh4[(j1 + row) * 4 + c]
                                : ll4[(j1 + row) * 4 + (c - 4)];
            }
        }

        // ---- epilogue: pass P stores m-frag P (all 8 warps active) ----
        const float4 lv = reinterpret_cast<const float4*>(lin_s)[lane];
        #pragma unroll
        for (int P = 0; P < 2; ++P) {
            {
                const uint32_t rr0 = mw * 16 + (lane >> 2);
                const uint32_t rr1 = rr0 + 8;
                #pragma unroll
                for (int n = 0; n < 8; ++n) {
                    const uint32_t ec = nw * 64 + n * 8 + 2 * (lane & 3);
                    const uint32_t chunk = ec >> 2;
                    const uint32_t off = (ec & 2) << 2;
                    const uint32_t a0 = sStage + rr0 * 512 + ((chunk ^ (rr0 & 7)) << 4) + off;
                    const uint32_t a1 = sStage + rr1 * 512 + ((chunk ^ (rr1 & 7)) << 4) + off;
                    asm volatile("st.shared.v2.f32 [%0], {%1,%2};"
                                 :: "r"(a0), "f"(acc[P][n][0]), "f"(acc[P][n][1]) : "memory");
                    asm volatile("st.shared.v2.f32 [%0], {%1,%2};"
                                 :: "r"(a1), "f"(acc[P][n][2]), "f"(acc[P][n][3]) : "memory");
                }
            }
            __syncthreads();
            #pragma unroll
            for (int it = 0; it < 8; ++it) {
                const int r2 = wid * 8 + it;
                const uint32_t la = sStage + r2 * 512 + (((uint32_t)(lane ^ (r2 & 7))) << 4);
                float v0, v1, v2, v3;
                asm volatile("ld.shared.v4.f32 {%0,%1,%2,%3}, [%4];"
                             : "=f"(v0), "=f"(v1), "=f"(v2), "=f"(v3) : "r"(la));
                float4 v;
                v.x = v0 + lv.x; v.y = v1 + lv.y; v.z = v2 + lv.z; v.w = v3 + lv.w;
                *reinterpret_cast<float4*>(out + ((size_t)i * L + j0 + P * 64 + r2) * E + lane * 4) = v;
            }
            // store prefetched A tile during first drain phase (A region is idle)
            if (P == 0 && has_next) {
                #pragma unroll
                for (int q = 0; q < 4; ++q) {
                    const int idx = tid + q * 256;
                    const int c = idx & 7;
                    const int row = idx >> 3;
                    *reinterpret_cast<uint4*>(smem + SOFF_A + row * RSTRIDE + c * 16) = pf[q];
                }
            }
            __syncthreads();
        }
    }
}

// ---------------- launch ----------------
extern "C" void kernel_launch(void* const* d_in, const int* in_sizes, int n_in,
                              void* d_out, int out_size)
{
    const float* act  = (const float*)d_in[0];
    const float* mask = (const float*)d_in[1];
    const float* nw   = (const float*)d_in[2];
    const float* nb   = (const float*)d_in[3];
    const float* wl   = (const float*)d_in[4];
    const float* bl   = (const float*)d_in[5];
    const float* wr   = (const float*)d_in[6];
    const float* br   = (const float*)d_in[7];
    const float* wo   = (const float*)d_in[8];
    const float* bo   = (const float*)d_in[9];
    float* out = (float*)d_out;

    cudaFuncSetAttribute(pair_kernel, cudaFuncAttributeMaxDynamicSharedMemorySize, SMEM_PAIR);

    ln_proj_kernel<<<L, 256>>>(act, mask, nw, nb, wl, bl, wr, br);
    pair_kernel<<<dim3(2, L), 256, SMEM_PAIR>>>(wo, bo, out);
}

// round 6
// speedup vs baseline: 1.4286x; 1.0684x over previous
#include <cuda_runtime.h>
#include <cuda_fp16.h>
#include <cstdint>

// Problem constants (B=1)
#define L 768
#define C_IN 384
#define D 32          // C_OUTER
#define E 128         // C_OUT
#define EPS 1e-5f

// ---------------- scratch (no allocations allowed) ----------------
__device__ float g_right[L * D];
__device__ __align__(16) __half g_lh[L * D];   // left hi (fp16)
__device__ __align__(16) __half g_ll[L * D];   // left lo (fp16)

// ================= PTX helpers =================
__device__ __forceinline__ uint32_t smem_u32(const void* p) {
    uint32_t a;
    asm("{ .reg .u64 t; cvta.to.shared.u64 t, %1; cvt.u32.u64 %0, t; }" : "=r"(a) : "l"(p));
    return a;
}
__device__ __forceinline__ void ldsm_x4(uint32_t* r, uint32_t addr) {
    asm volatile("ldmatrix.sync.aligned.m8n8.x4.shared.b16 {%0,%1,%2,%3}, [%4];"
                 : "=r"(r[0]), "=r"(r[1]), "=r"(r[2]), "=r"(r[3]) : "r"(addr));
}
__device__ __forceinline__ void mma16816(float* c, const uint32_t* a, const uint32_t* b) {
    asm volatile("mma.sync.aligned.m16n8k16.row.col.f32.f16.f16.f32 "
                 "{%0,%1,%2,%3}, {%4,%5,%6,%7}, {%8,%9}, {%0,%1,%2,%3};"
                 : "+f"(c[0]), "+f"(c[1]), "+f"(c[2]), "+f"(c[3])
                 : "r"(a[0]), "r"(a[1]), "r"(a[2]), "r"(a[3]), "r"(b[0]), "r"(b[1]));
}

// ---------------- Kernel A: LayerNorm + left/right projections ----------------
__global__ void __launch_bounds__(256) ln_proj_kernel(
    const float* __restrict__ act, const float* __restrict__ mask,
    const float* __restrict__ nw, const float* __restrict__ nb,
    const float* __restrict__ wl, const float* __restrict__ bl,
    const float* __restrict__ wr, const float* __restrict__ br)
{
    __shared__ float s_norm[C_IN];
    __shared__ float warp_sum[8];
    __shared__ float bcast;
    __shared__ float red[256];

    const int l = blockIdx.x;
    const int tid = threadIdx.x;
    const int lane = tid & 31;
    const int wid = tid >> 5;
    const float* arow = act + (size_t)l * C_IN;

    const float x0 = arow[tid];
    const float x1 = (tid < C_IN - 256) ? arow[256 + tid] : 0.0f;

    float s = x0 + x1;
    #pragma unroll
    for (int o = 16; o > 0; o >>= 1) s += __shfl_xor_sync(0xffffffffu, s, o);
    if (lane == 0) warp_sum[wid] = s;
    __syncthreads();
    if (tid == 0) {
        float t = 0.f;
        #pragma unroll
        for (int w = 0; w < 8; ++w) t += warp_sum[w];
        bcast = t * (1.0f / C_IN);
    }
    __syncthreads();
    const float mu = bcast;

    const float d0 = x0 - mu;
    const float d1 = (tid < C_IN - 256) ? (x1 - mu) : 0.0f;
    float v = d0 * d0 + d1 * d1;
    #pragma unroll
    for (int o = 16; o > 0; o >>= 1) v += __shfl_xor_sync(0xffffffffu, v, o);
    if (lane == 0) warp_sum[wid] = v;
    __syncthreads();
    if (tid == 0) {
        float t = 0.f;
        #pragma unroll
        for (int w = 0; w < 8; ++w) t += warp_sum[w];
        bcast = rsqrtf(t * (1.0f / C_IN) + EPS);
    }
    __syncthreads();
    const float rstd = bcast;

    s_norm[tid] = d0 * rstd * nw[tid] + nb[tid];
    if (tid < C_IN - 256)
        s_norm[256 + tid] = d1 * rstd * nw[256 + tid] + nb[256 + tid];
    __syncthreads();

    const int oc  = tid & 63;
    const int q   = tid >> 6;
    const int col = oc & 31;
    const float* w = (oc < 32) ? wl : wr;
    float dot = 0.0f;
    const int c0 = q * (C_IN / 4);
    #pragma unroll 8
    for (int c = c0; c < c0 + C_IN / 4; ++c)
        dot += s_norm[c] * w[c * D + col];
    red[tid] = dot;
    __syncthreads();
    if (tid < 128) red[tid] += red[tid + 128];
    __syncthreads();
    if (tid < 64) {
        const float vv = red[tid] + red[tid + 64];
        const float m = mask[l];
        const float val = m * (vv + ((oc < 32) ? bl[col] : br[col]));
        if (oc < 32) {
            const __half h = __float2half_rn(val);
            g_lh[l * D + col] = h;
            g_ll[l * D + col] = __float2half_rn(val - __half2float(h));
        } else {
            g_right[l * D + col] = val;
        }
    }
}

// ---------------- Kernel C: mma.sync batched GEMM (fp16 2-term, K=64) ----------------
// grid = (2 j-halves, L i), block = 256 (8 warps: 4 mw x 2 nw)
// A[j,k] = [hiL(32), loL(32)] fp16, row stride 144 B, DOUBLE BUFFERED
// B[e,k] = [hiB(32), hiB(32)] fp16 (resident all 3 tiles)
// out[i,j,e] = A.B + lin[i,e]   (direct st.global.v2 epilogue)
#define RSTRIDE 144
#define ATILE   18432
#define SOFF_LIN   0
#define SOFF_B     512
#define SOFF_A0    (512 + ATILE)
#define SOFF_A1    (512 + 2 * ATILE)
#define SMEM_PAIR  (512 + 3 * ATILE)   // 55808

__global__ void __launch_bounds__(256, 2) pair_kernel(
    const float* __restrict__ wo, const float* __restrict__ bo,
    float* __restrict__ out)
{
    extern __shared__ char smem[];
    __shared__ float r_s[D];
    const uint32_t sb = smem_u32(smem);
    const uint32_t sB = sb + SOFF_B;
    float* lin_s = reinterpret_cast<float*>(smem + SOFF_LIN);

    const int tid = threadIdx.x;
    const int wid = tid >> 5;
    const int lane = tid & 31;
    const int mw = wid & 3;          // m sub-row: 16 rows
    const int nw = wid >> 2;         // e half: cols nw*64
    const int i = blockIdx.y;
    const int jbase = blockIdx.x * 384;

    if (tid < D) r_s[tid] = g_right[i * D + tid];
    __syncthreads();

    // ---- build B tile (threads 0..127) + lin ----
    if (tid < E) {
        const int e = tid;
        float acc = 0.0f;
        alignas(16) __half hi[D];
        #pragma unroll
        for (int d = 0; d < D; ++d) {
            const float w1 = wo[d * E + e];
            const float w2 = wo[(D + d) * E + e];
            const float rd = r_s[d];
            const float x = fmaf(rd, w1, w2);
            hi[d] = __float2half_rn(x);
            acc = fmaf(rd, w2, acc);
        }
        lin_s[e] = bo[e] - acc;
        const uint4* h4 = reinterpret_cast<const uint4*>(hi);
        char* rowp = smem + SOFF_B + e * RSTRIDE;
        #pragma unroll
        for (int c = 0; c < 4; ++c) {
            *reinterpret_cast<uint4*>(rowp + c * 16)       = h4[c];
            *reinterpret_cast<uint4*>(rowp + 64 + c * 16)  = h4[c];
        }
    }

    const uint4* lh4 = reinterpret_cast<const uint4*>(g_lh);
    const uint4* ll4 = reinterpret_cast<const uint4*>(g_ll);

    // ---- build first A tile into buffer 0 ----
    #pragma unroll
    for (int q = 0; q < 4; ++q) {
        const int idx = tid + q * 256;
        const int c = idx & 7;
        const int row = idx >> 3;
        const uint4 v = (c < 4) ? lh4[(jbase + row) * 4 + c]
                                : ll4[(jbase + row) * 4 + (c - 4)];
        *reinterpret_cast<uint4*>(smem + SOFF_A0 + row * RSTRIDE + c * 16) = v;
    }
    __syncthreads();

    // per-lane lin pair for each n (constant over whole block)
    float2 lreg[8];
    #pragma unroll
    for (int n = 0; n < 8; ++n)
        lreg[n] = reinterpret_cast<const float2*>(lin_s)[nw * 32 + n * 4 + (lane & 3)];

    #pragma unroll
    for (int jt = 0; jt < 3; ++jt) {
        const int j0 = jbase + jt * 128;
        const uint32_t sA = sb + ((jt & 1) ? SOFF_A1 : SOFF_A0);
        const uint32_t sAnext = sb + ((jt & 1) ? SOFF_A0 : SOFF_A1);

        // ---- mainloop: 4 k-tiles of 16 ----
        float acc[2][8][4];
        #pragma unroll
        for (int m = 0; m < 2; ++m)
            #pragma unroll
            for (int n = 0; n < 8; ++n)
                #pragma unroll
                for (int q = 0; q < 4; ++q) acc[m][n][q] = 0.0f;

        #pragma unroll
        for (int kt = 0; kt < 4; ++kt) {
            const uint32_t kb = kt * 32;
            uint32_t bfr[8][2];
            #pragma unroll
            for (int p = 0; p < 4; ++p) {
                const uint32_t er = nw * 64 + p * 16;
                const uint32_t row = er + (lane & 7) + ((lane >> 4) << 3);
                const uint32_t addr = sB + row * RSTRIDE + kb + (((lane >> 3) & 1) << 4);
                uint32_t r[4];
                ldsm_x4(r, addr);
                bfr[2 * p][0] = r[0]; bfr[2 * p][1] = r[1];
                bfr[2 * p + 1][0] = r[2]; bfr[2 * p + 1][1] = r[3];
            }
            #pragma unroll
            for (int m = 0; m < 2; ++m) {
                const uint32_t jr = m * 64 + mw * 16 + (lane & 15);
                const uint32_t addr = sA + jr * RSTRIDE + kb + ((lane >> 4) << 4);
                uint32_t a[4];
                ldsm_x4(a, addr);
                #pragma unroll
                for (int n = 0; n < 8; ++n)
                    mma16816(acc[m][n], a, bfr[n]);
            }
        }

        // ---- prefetch next A tile (LDG issued before STG drain) ----
        uint4 pf[4];
        const bool has_next = (jt < 2);
        if (has_next) {
            const int j1 = j0 + 128;
            #pragma unroll
            for (int q = 0; q < 4; ++q) {
                const int idx = tid + q * 256;
                const int c = idx & 7;
                const int row = idx >> 3;
                pf[q] = (c < 4) ? lh4[(j1 + row) * 4 + c]
                                : ll4[(j1 + row) * 4 + (c - 4)];
            }
        }

        // ---- direct-STG epilogue (contiguous 32B per lane-quad) ----
        #pragma unroll
        for (int P = 0; P < 2; ++P) {
            const int r0 = P * 64 + mw * 16 + (lane >> 2);
            float* base0 = out + ((size_t)i * L + j0 + r0) * E + nw * 64 + 2 * (lane & 3);
            float* base1 = base0 + 8 * E;
            #pragma unroll
            for (int n = 0; n < 8; ++n) {
                float2 v0, v1;
                v0.x = acc[P][n][0] + lreg[n].x;  v0.y = acc[P][n][1] + lreg[n].y;
                v1.x = acc[P][n][2] + lreg[n].x;  v1.y = acc[P][n][3] + lreg[n].y;
                *reinterpret_cast<float2*>(base0 + n * 8) = v0;
                *reinterpret_cast<float2*>(base1 + n * 8) = v1;
            }
        }

        // ---- store prefetched A into the other buffer, single barrier ----
        if (has_next) {
            #pragma unroll
            for (int q = 0; q < 4; ++q) {
                const int idx = tid + q * 256;
                const int c = idx & 7;
                const int row = idx >> 3;
                *reinterpret_cast<uint4*>(reinterpret_cast<char*>(smem) +
                    (sAnext - sb) + row * RSTRIDE + c * 16) = pf[q];
            }
            __syncthreads();
        }
    }
}

// ---------------- launch ----------------
extern "C" void kernel_launch(void* const* d_in, const int* in_sizes, int n_in,
                              void* d_out, int out_size)
{
    const float* act  = (const float*)d_in[0];
    const float* mask = (const float*)d_in[1];
    const float* nw   = (const float*)d_in[2];
    const float* nb   = (const float*)d_in[3];
    const float* wl   = (const float*)d_in[4];
    const float* bl   = (const float*)d_in[5];
    const float* wr   = (const float*)d_in[6];
    const float* br   = (const float*)d_in[7];
    const float* wo   = (const float*)d_in[8];
    const float* bo   = (const float*)d_in[9];
    float* out = (float*)d_out;

    cudaFuncSetAttribute(pair_kernel, cudaFuncAttributeMaxDynamicSharedMemorySize, SMEM_PAIR);

    ln_proj_kernel<<<L, 256>>>(act, mask, nw, nb, wl, bl, wr, br);
    pair_kernel<<<dim3(2, L), 256, SMEM_PAIR>>>(wo, bo, out);
}

// round 7
// speedup vs baseline: 1.6211x; 1.1347x over previous
#include <cuda_runtime.h>
#include <cuda_fp16.h>
#include <cstdint>

// Problem constants (B=1)
#define L 768
#define C_IN 384
#define D 32          // C_OUTER
#define E 128         // C_OUT
#define EPS 1e-5f

// ---------------- scratch (no allocations allowed) ----------------
__device__ float g_right[L * D];
__device__ __align__(16) __half g_lh[L * D];   // left (fp16)

// ================= PTX helpers =================
__device__ __forceinline__ uint32_t smem_u32(const void* p) {
    uint32_t a;
    asm("{ .reg .u64 t; cvta.to.shared.u64 t, %1; cvt.u32.u64 %0, t; }" : "=r"(a) : "l"(p));
    return a;
}
__device__ __forceinline__ void ldsm_x4(uint32_t* r, uint32_t addr) {
    asm volatile("ldmatrix.sync.aligned.m8n8.x4.shared.b16 {%0,%1,%2,%3}, [%4];"
                 : "=r"(r[0]), "=r"(r[1]), "=r"(r[2]), "=r"(r[3]) : "r"(addr));
}
__device__ __forceinline__ void mma16816(float* c, const uint32_t* a, const uint32_t* b) {
    asm volatile("mma.sync.aligned.m16n8k16.row.col.f32.f16.f16.f32 "
                 "{%0,%1,%2,%3}, {%4,%5,%6,%7}, {%8,%9}, {%0,%1,%2,%3};"
                 : "+f"(c[0]), "+f"(c[1]), "+f"(c[2]), "+f"(c[3])
                 : "r"(a[0]), "r"(a[1]), "r"(a[2]), "r"(a[3]), "r"(b[0]), "r"(b[1]));
}

// ---------------- Kernel A: LayerNorm + left/right projections ----------------
__global__ void __launch_bounds__(256) ln_proj_kernel(
    const float* __restrict__ act, const float* __restrict__ mask,
    const float* __restrict__ nw, const float* __restrict__ nb,
    const float* __restrict__ wl, const float* __restrict__ bl,
    const float* __restrict__ wr, const float* __restrict__ br)
{
    __shared__ float s_norm[C_IN];
    __shared__ float warp_sum[8];
    __shared__ float bcast;
    __shared__ float red[256];

    const int l = blockIdx.x;
    const int tid = threadIdx.x;
    const int lane = tid & 31;
    const int wid = tid >> 5;
    const float* arow = act + (size_t)l * C_IN;

    const float x0 = arow[tid];
    const float x1 = (tid < C_IN - 256) ? arow[256 + tid] : 0.0f;

    float s = x0 + x1;
    #pragma unroll
    for (int o = 16; o > 0; o >>= 1) s += __shfl_xor_sync(0xffffffffu, s, o);
    if (lane == 0) warp_sum[wid] = s;
    __syncthreads();
    if (tid == 0) {
        float t = 0.f;
        #pragma unroll
        for (int w = 0; w < 8; ++w) t += warp_sum[w];
        bcast = t * (1.0f / C_IN);
    }
    __syncthreads();
    const float mu = bcast;

    const float d0 = x0 - mu;
    const float d1 = (tid < C_IN - 256) ? (x1 - mu) : 0.0f;
    float v = d0 * d0 + d1 * d1;
    #pragma unroll
    for (int o = 16; o > 0; o >>= 1) v += __shfl_xor_sync(0xffffffffu, v, o);
    if (lane == 0) warp_sum[wid] = v;
    __syncthreads();
    if (tid == 0) {
        float t = 0.f;
        #pragma unroll
        for (int w = 0; w < 8; ++w) t += warp_sum[w];
        bcast = rsqrtf(t * (1.0f / C_IN) + EPS);
    }
    __syncthreads();
    const float rstd = bcast;

    s_norm[tid] = d0 * rstd * nw[tid] + nb[tid];
    if (tid < C_IN - 256)
        s_norm[256 + tid] = d1 * rstd * nw[256 + tid] + nb[256 + tid];
    __syncthreads();

    const int oc  = tid & 63;
    const int q   = tid >> 6;
    const int col = oc & 31;
    const float* w = (oc < 32) ? wl : wr;
    float dot = 0.0f;
    const int c0 = q * (C_IN / 4);
    #pragma unroll 8
    for (int c = c0; c < c0 + C_IN / 4; ++c)
        dot += s_norm[c] * w[c * D + col];
    red[tid] = dot;
    __syncthreads();
    if (tid < 128) red[tid] += red[tid + 128];
    __syncthreads();
    if (tid < 64) {
        const float vv = red[tid] + red[tid + 64];
        const float m = mask[l];
        const float val = m * (vv + ((oc < 32) ? bl[col] : br[col]));
        if (oc < 32) g_lh[l * D + col] = __float2half_rn(val);
        else         g_right[l * D + col] = val;
    }
}

// ---------------- Kernel C: mma.sync batched GEMM (fp16, K=32) ----------------
// grid = (2 j-halves, L i), block = 256 (8 warps: 4 mw x 2 nw)
// A[j,k] fp16 32 halfs/row, stride 80 B, DOUBLE BUFFERED
// B[e,k] fp16 32 halfs/row, stride 80 B (resident all 3 tiles)
// out[i,j,e] = A.B + lin[i,e]   (shuffle-merged st.global.v4 epilogue)
#define RSTRIDE 80
#define TILEB   10240
#define SOFF_LIN   0
#define SOFF_B     512
#define SOFF_A0    (512 + TILEB)
#define SOFF_A1    (512 + 2 * TILEB)
#define SMEM_PAIR  (512 + 3 * TILEB)   // 31232

__global__ void __launch_bounds__(256, 2) pair_kernel(
    const float* __restrict__ wo, const float* __restrict__ bo,
    float* __restrict__ out)
{
    extern __shared__ char smem[];
    __shared__ float r_s[D];
    const uint32_t sb = smem_u32(smem);
    const uint32_t sB = sb + SOFF_B;
    float* lin_s = reinterpret_cast<float*>(smem + SOFF_LIN);

    const int tid = threadIdx.x;
    const int wid = tid >> 5;
    const int lane = tid & 31;
    const int mw = wid & 3;          // m sub-row: 16 rows
    const int nw = wid >> 2;         // e half: cols nw*64
    const int i = blockIdx.y;
    const int jbase = blockIdx.x * 384;

    if (tid < D) r_s[tid] = g_right[i * D + tid];
    __syncthreads();

    // ---- build B tile (threads 0..127) + lin ----
    if (tid < E) {
        const int e = tid;
        float acc = 0.0f;
        alignas(16) __half hi[D];
        #pragma unroll
        for (int d = 0; d < D; ++d) {
            const float w1 = wo[d * E + e];
            const float w2 = wo[(D + d) * E + e];
            const float rd = r_s[d];
            hi[d] = __float2half_rn(fmaf(rd, w1, w2));
            acc = fmaf(rd, w2, acc);
        }
        lin_s[e] = bo[e] - acc;
        const uint4* h4 = reinterpret_cast<const uint4*>(hi);
        char* rowp = smem + SOFF_B + e * RSTRIDE;
        #pragma unroll
        for (int c = 0; c < 4; ++c)
            *reinterpret_cast<uint4*>(rowp + c * 16) = h4[c];
    }

    const uint4* lh4 = reinterpret_cast<const uint4*>(g_lh);

    // ---- build first A tile into buffer 0 (128 rows x 4 chunks) ----
    #pragma unroll
    for (int q = 0; q < 2; ++q) {
        const int idx = tid + q * 256;
        const int c = idx & 3;
        const int row = idx >> 2;
        *reinterpret_cast<uint4*>(smem + SOFF_A0 + row * RSTRIDE + c * 16) =
            lh4[(jbase + row) * 4 + c];
    }
    __syncthreads();

    // per-lane lin pair for each n (column-indexed, constant over block)
    float2 lreg[8];
    #pragma unroll
    for (int n = 0; n < 8; ++n)
        lreg[n] = reinterpret_cast<const float2*>(lin_s)[nw * 32 + n * 4 + (lane & 3)];

    #pragma unroll
    for (int jt = 0; jt < 3; ++jt) {
        const int j0 = jbase + jt * 128;
        const uint32_t sA = sb + ((jt & 1) ? SOFF_A1 : SOFF_A0);
        const uint32_t sAnext = sb + ((jt & 1) ? SOFF_A0 : SOFF_A1);

        // ---- mainloop: 2 k-tiles of 16 ----
        float acc[2][8][4];
        #pragma unroll
        for (int m = 0; m < 2; ++m)
            #pragma unroll
            for (int n = 0; n < 8; ++n)
                #pragma unroll
                for (int q = 0; q < 4; ++q) acc[m][n][q] = 0.0f;

        #pragma unroll
        for (int kt = 0; kt < 2; ++kt) {
            const uint32_t kb = kt * 32;
            uint32_t bfr[8][2];
            #pragma unroll
            for (int p = 0; p < 4; ++p) {
                const uint32_t er = nw * 64 + p * 16;
                const uint32_t row = er + (lane & 7) + ((lane >> 4) << 3);
                const uint32_t addr = sB + row * RSTRIDE + kb + (((lane >> 3) & 1) << 4);
                uint32_t r[4];
                ldsm_x4(r, addr);
                bfr[2 * p][0] = r[0]; bfr[2 * p][1] = r[1];
                bfr[2 * p + 1][0] = r[2]; bfr[2 * p + 1][1] = r[3];
            }
            #pragma unroll
            for (int m = 0; m < 2; ++m) {
                const uint32_t jr = m * 64 + mw * 16 + (lane & 15);
                const uint32_t addr = sA + jr * RSTRIDE + kb + ((lane >> 4) << 4);
                uint32_t a[4];
                ldsm_x4(a, addr);
                #pragma unroll
                for (int n = 0; n < 8; ++n)
                    mma16816(acc[m][n], a, bfr[n]);
            }
        }

        // ---- prefetch next A tile (LDG before STG drain) ----
        uint4 pf[2];
        const bool has_next = (jt < 2);
        if (has_next) {
            const int j1 = j0 + 128;
            #pragma unroll
            for (int q = 0; q < 2; ++q) {
                const int idx = tid + q * 256;
                pf[q] = lh4[(j1 + (idx >> 2)) * 4 + (idx & 3)];
            }
        }

        // ---- shuffle-merged STG.128 epilogue ----
        // even lanes own row r0, odd lanes own row r0+8; 4 contiguous floats each
        #pragma unroll
        for (int P = 0; P < 2; ++P) {
            const int r0 = P * 64 + mw * 16 + (lane >> 2);
            const int rowA = r0 + (lane & 1) * 8;
            float* basep = out + ((size_t)i * L + j0 + rowA) * E
                         + nw * 64 + ((lane >> 1) & 1) * 4;
            #pragma unroll
            for (int n = 0; n < 8; ++n) {
                float2 v01, v23;
                v01.x = acc[P][n][0] + lreg[n].x;  v01.y = acc[P][n][1] + lreg[n].y;
                v23.x = acc[P][n][2] + lreg[n].x;  v23.y = acc[P][n][3] + lreg[n].y;
                const float2 send = (lane & 1) ? v01 : v23;
                float2 recv;
                recv.x = __shfl_xor_sync(0xffffffffu, send.x, 1);
                recv.y = __shfl_xor_sync(0xffffffffu, send.y, 1);
                float4 v;
                if (lane & 1) { v.x = recv.x; v.y = recv.y; v.z = v23.x; v.w = v23.y; }
                else          { v.x = v01.x; v.y = v01.y; v.z = recv.x; v.w = recv.y; }
                *reinterpret_cast<float4*>(basep + n * 8) = v;
            }
        }

        // ---- store prefetched A into the other buffer, single barrier ----
        if (has_next) {
            #pragma unroll
            for (int q = 0; q < 2; ++q) {
                const int idx = tid + q * 256;
                *reinterpret_cast<uint4*>(reinterpret_cast<char*>(smem) +
                    (sAnext - sb) + (idx >> 2) * RSTRIDE + (idx & 3) * 16) = pf[q];
            }
            __syncthreads();
        }
    }
}

// ---------------- launch ----------------
extern "C" void kernel_launch(void* const* d_in, const int* in_sizes, int n_in,
                              void* d_out, int out_size)
{
    const float* act  = (const float*)d_in[0];
    const float* mask = (const float*)d_in[1];
    const float* nw   = (const float*)d_in[2];
    const float* nb   = (const float*)d_in[3];
    const float* wl   = (const float*)d_in[4];
    const float* bl   = (const float*)d_in[5];
    const float* wr   = (const float*)d_in[6];
    const float* br   = (const float*)d_in[7];
    const float* wo   = (const float*)d_in[8];
    const float* bo   = (const float*)d_in[9];
    float* out = (float*)d_out;

    cudaFuncSetAttribute(pair_kernel, cudaFuncAttributeMaxDynamicSharedMemorySize, SMEM_PAIR);

    ln_proj_kernel<<<L, 256>>>(act, mask, nw, nb, wl, bl, wr, br);
    pair_kernel<<<dim3(2, L), 256, SMEM_PAIR>>>(wo, bo, out);
}

// round 8
// speedup vs baseline: 1.7843x; 1.1007x over previous
#include <cuda_runtime.h>
#include <cuda_fp16.h>
#include <cstdint>

// Problem constants (B=1)
#define L 768
#define C_IN 384
#define D 32          // C_OUTER
#define E 128         // C_OUT
#define EPS 1e-5f

// ---------------- scratch (no allocations allowed) ----------------
__device__ float g_right[L * D];
__device__ __align__(16) __half g_lh[L * D];   // left (fp16)

// ================= PTX helpers =================
__device__ __forceinline__ uint32_t smem_u32(const void* p) {
    uint32_t a;
    asm("{ .reg .u64 t; cvta.to.shared.u64 t, %1; cvt.u32.u64 %0, t; }" : "=r"(a) : "l"(p));
    return a;
}
__device__ __forceinline__ void ldsm_x4(uint32_t* r, uint32_t addr) {
    asm volatile("ldmatrix.sync.aligned.m8n8.x4.shared.b16 {%0,%1,%2,%3}, [%4];"
                 : "=r"(r[0]), "=r"(r[1]), "=r"(r[2]), "=r"(r[3]) : "r"(addr));
}
__device__ __forceinline__ void mma16816(float* c, const uint32_t* a, const uint32_t* b) {
    asm volatile("mma.sync.aligned.m16n8k16.row.col.f32.f16.f16.f32 "
                 "{%0,%1,%2,%3}, {%4,%5,%6,%7}, {%8,%9}, {%0,%1,%2,%3};"
                 : "+f"(c[0]), "+f"(c[1]), "+f"(c[2]), "+f"(c[3])
                 : "r"(a[0]), "r"(a[1]), "r"(a[2]), "r"(a[3]), "r"(b[0]), "r"(b[1]));
}
#define CP_ASYNC16(dst, src) \
    asm volatile("cp.async.ca.shared.global [%0], [%1], 16;" :: "r"(dst), "l"(src) : "memory")
#define CP_COMMIT()  asm volatile("cp.async.commit_group;" ::: "memory")
#define CP_WAIT0()   asm volatile("cp.async.wait_group 0;" ::: "memory")

// ---------------- Kernel A: LayerNorm + left/right projections ----------------
__global__ void __launch_bounds__(256) ln_proj_kernel(
    const float* __restrict__ act, const float* __restrict__ mask,
    const float* __restrict__ nw, const float* __restrict__ nb,
    const float* __restrict__ wl, const float* __restrict__ bl,
    const float* __restrict__ wr, const float* __restrict__ br)
{
    __shared__ float s_norm[C_IN];
    __shared__ float warp_sum[8];
    __shared__ float bcast;
    __shared__ float red[256];

    const int l = blockIdx.x;
    const int tid = threadIdx.x;
    const int lane = tid & 31;
    const int wid = tid >> 5;
    const float* arow = act + (size_t)l * C_IN;

    const float x0 = arow[tid];
    const float x1 = (tid < C_IN - 256) ? arow[256 + tid] : 0.0f;

    float s = x0 + x1;
    #pragma unroll
    for (int o = 16; o > 0; o >>= 1) s += __shfl_xor_sync(0xffffffffu, s, o);
    if (lane == 0) warp_sum[wid] = s;
    __syncthreads();
    if (tid == 0) {
        float t = 0.f;
        #pragma unroll
        for (int w = 0; w < 8; ++w) t += warp_sum[w];
        bcast = t * (1.0f / C_IN);
    }
    __syncthreads();
    const float mu = bcast;

    const float d0 = x0 - mu;
    const float d1 = (tid < C_IN - 256) ? (x1 - mu) : 0.0f;
    float v = d0 * d0 + d1 * d1;
    #pragma unroll
    for (int o = 16; o > 0; o >>= 1) v += __shfl_xor_sync(0xffffffffu, v, o);
    if (lane == 0) warp_sum[wid] = v;
    __syncthreads();
    if (tid == 0) {
        float t = 0.f;
        #pragma unroll
        for (int w = 0; w < 8; ++w) t += warp_sum[w];
        bcast = rsqrtf(t * (1.0f / C_IN) + EPS);
    }
    __syncthreads();
    const float rstd = bcast;

    s_norm[tid] = d0 * rstd * nw[tid] + nb[tid];
    if (tid < C_IN - 256)
        s_norm[256 + tid] = d1 * rstd * nw[256 + tid] + nb[256 + tid];
    __syncthreads();

    const int oc  = tid & 63;
    const int q   = tid >> 6;
    const int col = oc & 31;
    const float* w = (oc < 32) ? wl : wr;
    float dot = 0.0f;
    const int c0 = q * (C_IN / 4);
    #pragma unroll 8
    for (int c = c0; c < c0 + C_IN / 4; ++c)
        dot += s_norm[c] * w[c * D + col];
    red[tid] = dot;
    __syncthreads();
    if (tid < 128) red[tid] += red[tid + 128];
    __syncthreads();
    if (tid < 64) {
        const float vv = red[tid] + red[tid + 64];
        const float m = mask[l];
        const float val = m * (vv + ((oc < 32) ? bl[col] : br[col]));
        if (oc < 32) g_lh[l * D + col] = __float2half_rn(val);
        else         g_right[l * D + col] = val;
    }
}

// ---------------- Kernel C: mma.sync batched GEMM (fp16, K=32) ----------------
// grid = L (one block per i), block = 256 (8 warps: 4 mw x 2 nw), 6 j-tiles
// A[j,k] fp16 32 halfs/row, stride 80 B, double-buffered via cp.async
// B[e,k] fp16 -> fragments hoisted to registers once per block
// out[i,j,e] = A.B + lin[i,e]   (direct st.global.v2 epilogue)
#define RSTRIDE 80
#define TILEB   10240
#define SOFF_LIN   0
#define SOFF_B     512
#define SOFF_A0    (512 + TILEB)
#define SOFF_A1    (512 + 2 * TILEB)
#define SMEM_PAIR  (512 + 3 * TILEB)   // 31232

__global__ void __launch_bounds__(256, 2) pair_kernel(
    const float* __restrict__ wo, const float* __restrict__ bo,
    float* __restrict__ out)
{
    extern __shared__ char smem[];
    __shared__ float r_s[D];
    const uint32_t sb = smem_u32(smem);
    const uint32_t sB = sb + SOFF_B;
    float* lin_s = reinterpret_cast<float*>(smem + SOFF_LIN);

    const int tid = threadIdx.x;
    const int wid = tid >> 5;
    const int lane = tid & 31;
    const int mw = wid & 3;          // m sub-row: 16 rows
    const int nw = wid >> 2;         // e half: cols nw*64
    const int i = blockIdx.x;

    if (tid < D) r_s[tid] = g_right[i * D + tid];
    __syncthreads();

    // ---- build B tile in smem (threads 0..127) + lin ----
    if (tid < E) {
        const int e = tid;
        float acc = 0.0f;
        alignas(16) __half hi[D];
        #pragma unroll
        for (int d = 0; d < D; ++d) {
            const float w1 = wo[d * E + e];
            const float w2 = wo[(D + d) * E + e];
            const float rd = r_s[d];
            hi[d] = __float2half_rn(fmaf(rd, w1, w2));
            acc = fmaf(rd, w2, acc);
        }
        lin_s[e] = bo[e] - acc;
        const uint4* h4 = reinterpret_cast<const uint4*>(hi);
        char* rowp = smem + SOFF_B + e * RSTRIDE;
        #pragma unroll
        for (int c = 0; c < 4; ++c)
            *reinterpret_cast<uint4*>(rowp + c * 16) = h4[c];
    }

    // ---- first A tile via cp.async into buffer 0 ----
    const __half* gA = g_lh;   // row j: 32 halfs = 64 B
    #pragma unroll
    for (int q = 0; q < 2; ++q) {
        const int idx = tid + q * 256;
        const int row = idx >> 2, c = idx & 3;
        CP_ASYNC16(sb + SOFF_A0 + row * RSTRIDE + c * 16,
                   (const char*)(gA + row * D) + c * 16);
    }
    CP_COMMIT();
    CP_WAIT0();
    __syncthreads();

    // ---- hoist B fragments to registers (same for all 6 tiles) ----
    uint32_t bfr[2][8][2];
    #pragma unroll
    for (int kt = 0; kt < 2; ++kt) {
        #pragma unroll
        for (int p = 0; p < 4; ++p) {
            const uint32_t er = nw * 64 + p * 16;
            const uint32_t row = er + (lane & 7) + ((lane >> 4) << 3);
            const uint32_t addr = sB + row * RSTRIDE + kt * 32 + (((lane >> 3) & 1) << 4);
            uint32_t r[4];
            ldsm_x4(r, addr);
            bfr[kt][2 * p][0] = r[0]; bfr[kt][2 * p][1] = r[1];
            bfr[kt][2 * p + 1][0] = r[2]; bfr[kt][2 * p + 1][1] = r[3];
        }
    }

    // per-lane lin pair for each n (column-indexed, constant over block)
    float2 lreg[8];
    #pragma unroll
    for (int n = 0; n < 8; ++n)
        lreg[n] = reinterpret_cast<const float2*>(lin_s)[nw * 32 + n * 4 + (lane & 3)];

    for (int jt = 0; jt < 6; ++jt) {
        const int j0 = jt * 128;
        const uint32_t sA = sb + ((jt & 1) ? SOFF_A1 : SOFF_A0);
        const uint32_t sAnext = sb + ((jt & 1) ? SOFF_A0 : SOFF_A1);

        // ---- mainloop: 2 k-tiles of 16 ----
        float acc[2][8][4];
        #pragma unroll
        for (int m = 0; m < 2; ++m)
            #pragma unroll
            for (int n = 0; n < 8; ++n)
                #pragma unroll
                for (int q = 0; q < 4; ++q) acc[m][n][q] = 0.0f;

        #pragma unroll
        for (int kt = 0; kt < 2; ++kt) {
            #pragma unroll
            for (int m = 0; m < 2; ++m) {
                const uint32_t jr = m * 64 + mw * 16 + (lane & 15);
                const uint32_t addr = sA + jr * RSTRIDE + kt * 32 + ((lane >> 4) << 4);
                uint32_t a[4];
                ldsm_x4(a, addr);
                #pragma unroll
                for (int n = 0; n < 8; ++n)
                    mma16816(acc[m][n], a, bfr[kt][n]);
            }
        }

        // ---- prefetch next A tile via cp.async (overlaps epilogue stores) ----
        const bool has_next = (jt < 5);
        if (has_next) {
            const int j1 = j0 + 128;
            #pragma unroll
            for (int q = 0; q < 2; ++q) {
                const int idx = tid + q * 256;
                const int row = idx >> 2, c = idx & 3;
                CP_ASYNC16(sAnext + row * RSTRIDE + c * 16,
                           (const char*)(gA + (j1 + row) * D) + c * 16);
            }
            CP_COMMIT();
        }

        // ---- direct STG.64 epilogue ----
        #pragma unroll
        for (int P = 0; P < 2; ++P) {
            const int r0 = P * 64 + mw * 16 + (lane >> 2);
            float* base0 = out + ((size_t)i * L + j0 + r0) * E + nw * 64 + 2 * (lane & 3);
            float* base1 = base0 + 8 * E;
            #pragma unroll
            for (int n = 0; n < 8; ++n) {
                float2 v0, v1;
                v0.x = acc[P][n][0] + lreg[n].x;  v0.y = acc[P][n][1] + lreg[n].y;
                v1.x = acc[P][n][2] + lreg[n].x;  v1.y = acc[P][n][3] + lreg[n].y;
                *reinterpret_cast<float2*>(base0 + n * 8) = v0;
                *reinterpret_cast<float2*>(base1 + n * 8) = v1;
            }
        }

        if (has_next) {
            CP_WAIT0();
            __syncthreads();
        }
    }
}

// ---------------- launch ----------------
extern "C" void kernel_launch(void* const* d_in, const int* in_sizes, int n_in,
                              void* d_out, int out_size)
{
    const float* act  = (const float*)d_in[0];
    const float* mask = (const float*)d_in[1];
    const float* nw   = (const float*)d_in[2];
    const float* nb   = (const float*)d_in[3];
    const float* wl   = (const float*)d_in[4];
    const float* bl   = (const float*)d_in[5];
    const float* wr   = (const float*)d_in[6];
    const float* br   = (const float*)d_in[7];
    const float* wo   = (const float*)d_in[8];
    const float* bo   = (const float*)d_in[9];
    float* out = (float*)d_out;

    cudaFuncSetAttribute(pair_kernel, cudaFuncAttributeMaxDynamicSharedMemorySize, SMEM_PAIR);

    ln_proj_kernel<<<L, 256>>>(act, mask, nw, nb, wl, bl, wr, br);
    pair_kernel<<<L, 256, SMEM_PAIR>>>(wo, bo, out);
}

// round 9
// speedup vs baseline: 1.7951x; 1.0060x over previous
#include <cuda_runtime.h>
#include <cuda_fp16.h>
#include <cstdint>

// Problem constants (B=1)
#define L 768
#define C_IN 384
#define D 32          // C_OUTER
#define E 128         // C_OUT
#define EPS 1e-5f

// ---------------- scratch (no allocations allowed) ----------------
__device__ float g_right[L * D];
__device__ __align__(16) __half g_lh[L * D];   // left (fp16)

// ================= PTX helpers =================
__device__ __forceinline__ uint32_t smem_u32(const void* p) {
    uint32_t a;
    asm("{ .reg .u64 t; cvta.to.shared.u64 t, %1; cvt.u32.u64 %0, t; }" : "=r"(a) : "l"(p));
    return a;
}
__device__ __forceinline__ void ldsm_x4(uint32_t* r, uint32_t addr) {
    asm volatile("ldmatrix.sync.aligned.m8n8.x4.shared.b16 {%0,%1,%2,%3}, [%4];"
                 : "=r"(r[0]), "=r"(r[1]), "=r"(r[2]), "=r"(r[3]) : "r"(addr));
}
__device__ __forceinline__ void mma16816(float* c, const uint32_t* a, const uint32_t* b) {
    asm volatile("mma.sync.aligned.m16n8k16.row.col.f32.f16.f16.f32 "
                 "{%0,%1,%2,%3}, {%4,%5,%6,%7}, {%8,%9}, {%0,%1,%2,%3};"
                 : "+f"(c[0]), "+f"(c[1]), "+f"(c[2]), "+f"(c[3])
                 : "r"(a[0]), "r"(a[1]), "r"(a[2]), "r"(a[3]), "r"(b[0]), "r"(b[1]));
}
#define CP_ASYNC16(dst, src) \
    asm volatile("cp.async.ca.shared.global [%0], [%1], 16;" :: "r"(dst), "l"(src) : "memory")
#define CP_COMMIT()  asm volatile("cp.async.commit_group;" ::: "memory")
#define CP_WAIT0()   asm volatile("cp.async.wait_group 0;" ::: "memory")

// ---------------- Kernel A: LayerNorm + left/right projections ----------------
__global__ void __launch_bounds__(256) ln_proj_kernel(
    const float* __restrict__ act, const float* __restrict__ mask,
    const float* __restrict__ nw, const float* __restrict__ nb,
    const float* __restrict__ wl, const float* __restrict__ bl,
    const float* __restrict__ wr, const float* __restrict__ br)
{
    __shared__ float s_norm[C_IN];
    __shared__ float warp_sum[8];
    __shared__ float bcast;
    __shared__ float red[256];

    const int l = blockIdx.x;
    const int tid = threadIdx.x;
    const int lane = tid & 31;
    const int wid = tid >> 5;
    const float* arow = act + (size_t)l * C_IN;

    const float x0 = arow[tid];
    const float x1 = (tid < C_IN - 256) ? arow[256 + tid] : 0.0f;

    float s = x0 + x1;
    #pragma unroll
    for (int o = 16; o > 0; o >>= 1) s += __shfl_xor_sync(0xffffffffu, s, o);
    if (lane == 0) warp_sum[wid] = s;
    __syncthreads();
    if (tid == 0) {
        float t = 0.f;
        #pragma unroll
        for (int w = 0; w < 8; ++w) t += warp_sum[w];
        bcast = t * (1.0f / C_IN);
    }
    __syncthreads();
    const float mu = bcast;

    const float d0 = x0 - mu;
    const float d1 = (tid < C_IN - 256) ? (x1 - mu) : 0.0f;
    float v = d0 * d0 + d1 * d1;
    #pragma unroll
    for (int o = 16; o > 0; o >>= 1) v += __shfl_xor_sync(0xffffffffu, v, o);
    if (lane == 0) warp_sum[wid] = v;
    __syncthreads();
    if (tid == 0) {
        float t = 0.f;
        #pragma unroll
        for (int w = 0; w < 8; ++w) t += warp_sum[w];
        bcast = rsqrtf(t * (1.0f / C_IN) + EPS);
    }
    __syncthreads();
    const float rstd = bcast;

    s_norm[tid] = d0 * rstd * nw[tid] + nb[tid];
    if (tid < C_IN - 256)
        s_norm[256 + tid] = d1 * rstd * nw[256 + tid] + nb[256 + tid];
    __syncthreads();

    const int oc  = tid & 63;
    const int q   = tid >> 6;
    const int col = oc & 31;
    const float* w = (oc < 32) ? wl : wr;
    float dot = 0.0f;
    const int c0 = q * (C_IN / 4);
    #pragma unroll 8
    for (int c = c0; c < c0 + C_IN / 4; ++c)
        dot += s_norm[c] * w[c * D + col];
    red[tid] = dot;
    __syncthreads();
    if (tid < 128) red[tid] += red[tid + 128];
    __syncthreads();
    if (tid < 64) {
        const float vv = red[tid] + red[tid + 64];
        const float m = mask[l];
        const float val = m * (vv + ((oc < 32) ? bl[col] : br[col]));
        if (oc < 32) g_lh[l * D + col] = __float2half_rn(val);
        else         g_right[l * D + col] = val;
    }
}

// ---------------- Kernel C: mma.sync batched GEMM (fp16, K=32) ----------------
// grid = L (one block per i), block = 256 (8 warps: 4 mw x 2 nw), 6 j-tiles
// A[j,k] fp16 32 halfs/row, stride 80 B, double-buffered via cp.async
// B[e,k] fp16 -> fragments hoisted to registers once per block
// out[i,j,e] = A.B + lin[i,e]   (direct st.global.v2 epilogue)
#define RSTRIDE 80
#define TILEB   10240
#define SOFF_LIN   0
#define SOFF_B     512
#define SOFF_A0    (512 + TILEB)
#define SOFF_A1    (512 + 2 * TILEB)
#define SMEM_PAIR  (512 + 3 * TILEB)   // 31232

__global__ void __launch_bounds__(256, 2) pair_kernel(
    const float* __restrict__ wo, const float* __restrict__ bo,
    float* __restrict__ out)
{
    extern __shared__ char smem[];
    __shared__ float r_s[D];
    const uint32_t sb = smem_u32(smem);
    const uint32_t sB = sb + SOFF_B;
    float* lin_s = reinterpret_cast<float*>(smem + SOFF_LIN);

    const int tid = threadIdx.x;
    const int wid = tid >> 5;
    const int lane = tid & 31;
    const int mw = wid & 3;          // m sub-row: 16 rows
    const int nw = wid >> 2;         // e half: cols nw*64
    const int i = blockIdx.x;

    if (tid < D) r_s[tid] = g_right[i * D + tid];
    __syncthreads();

    // ---- build B tile in smem (threads 0..127) + lin ----
    if (tid < E) {
        const int e = tid;
        float acc = 0.0f;
        alignas(16) __half hi[D];
        #pragma unroll
        for (int d = 0; d < D; ++d) {
            const float w1 = wo[d * E + e];
            const float w2 = wo[(D + d) * E + e];
            const float rd = r_s[d];
            hi[d] = __float2half_rn(fmaf(rd, w1, w2));
            acc = fmaf(rd, w2, acc);
        }
        lin_s[e] = bo[e] - acc;
        const uint4* h4 = reinterpret_cast<const uint4*>(hi);
        char* rowp = smem + SOFF_B + e * RSTRIDE;
        #pragma unroll
        for (int c = 0; c < 4; ++c)
            *reinterpret_cast<uint4*>(rowp + c * 16) = h4[c];
    }

    // ---- first A tile via cp.async into buffer 0 ----
    const __half* gA = g_lh;   // row j: 32 halfs = 64 B
    #pragma unroll
    for (int q = 0; q < 2; ++q) {
        const int idx = tid + q * 256;
        const int row = idx >> 2, c = idx & 3;
        CP_ASYNC16(sb + SOFF_A0 + row * RSTRIDE + c * 16,
                   (const char*)(gA + row * D) + c * 16);
    }
    CP_COMMIT();
    CP_WAIT0();
    __syncthreads();

    // ---- hoist B fragments to registers (same for all 6 tiles) ----
    uint32_t bfr[2][8][2];
    #pragma unroll
    for (int kt = 0; kt < 2; ++kt) {
        #pragma unroll
        for (int p = 0; p < 4; ++p) {
            const uint32_t er = nw * 64 + p * 16;
            const uint32_t row = er + (lane & 7) + ((lane >> 4) << 3);
            const uint32_t addr = sB + row * RSTRIDE + kt * 32 + (((lane >> 3) & 1) << 4);
            uint32_t r[4];
            ldsm_x4(r, addr);
            bfr[kt][2 * p][0] = r[0]; bfr[kt][2 * p][1] = r[1];
            bfr[kt][2 * p + 1][0] = r[2]; bfr[kt][2 * p + 1][1] = r[3];
        }
    }

    // per-lane lin pair for each n (column-indexed, constant over block)
    float2 lreg[8];
    #pragma unroll
    for (int n = 0; n < 8; ++n)
        lreg[n] = reinterpret_cast<const float2*>(lin_s)[nw * 32 + n * 4 + (lane & 3)];

    for (int jt = 0; jt < 6; ++jt) {
        const int j0 = jt * 128;
        const uint32_t sA = sb + ((jt & 1) ? SOFF_A1 : SOFF_A0);
        const uint32_t sAnext = sb + ((jt & 1) ? SOFF_A0 : SOFF_A1);

        // ---- mainloop: 2 k-tiles of 16 ----
        float acc[2][8][4];
        #pragma unroll
        for (int m = 0; m < 2; ++m)
            #pragma unroll
            for (int n = 0; n < 8; ++n)
                #pragma unroll
                for (int q = 0; q < 4; ++q) acc[m][n][q] = 0.0f;

        #pragma unroll
        for (int kt = 0; kt < 2; ++kt) {
            #pragma unroll
            for (int m = 0; m < 2; ++m) {
                const uint32_t jr = m * 64 + mw * 16 + (lane & 15);
                const uint32_t addr = sA + jr * RSTRIDE + kt * 32 + ((lane >> 4) << 4);
                uint32_t a[4];
                ldsm_x4(a, addr);
                #pragma unroll
                for (int n = 0; n < 8; ++n)
                    mma16816(acc[m][n], a, bfr[kt][n]);
            }
        }

        // ---- prefetch next A tile via cp.async (overlaps epilogue stores) ----
        const bool has_next = (jt < 5);
        if (has_next) {
            const int j1 = j0 + 128;
            #pragma unroll
            for (int q = 0; q < 2; ++q) {
                const int idx = tid + q * 256;
                const int row = idx >> 2, c = idx & 3;
                CP_ASYNC16(sAnext + row * RSTRIDE + c * 16,
                           (const char*)(gA + (j1 + row) * D) + c * 16);
            }
            CP_COMMIT();
        }

        // ---- direct STG.64 epilogue ----
        #pragma unroll
        for (int P = 0; P < 2; ++P) {
            const int r0 = P * 64 + mw * 16 + (lane >> 2);
            float* base0 = out + ((size_t)i * L + j0 + r0) * E + nw * 64 + 2 * (lane & 3);
            float* base1 = base0 + 8 * E;
            #pragma unroll
            for (int n = 0; n < 8; ++n) {
                float2 v0, v1;
                v0.x = acc[P][n][0] + lreg[n].x;  v0.y = acc[P][n][1] + lreg[n].y;
                v1.x = acc[P][n][2] + lreg[n].x;  v1.y = acc[P][n][3] + lreg[n].y;
                *reinterpret_cast<float2*>(base0 + n * 8) = v0;
                *reinterpret_cast<float2*>(base1 + n * 8) = v1;
            }
        }

        if (has_next) {
            CP_WAIT0();
            __syncthreads();
        }
    }
}

// ---------------- launch ----------------
extern "C" void kernel_launch(void* const* d_in, const int* in_sizes, int n_in,
                              void* d_out, int out_size)
{
    const float* act  = (const float*)d_in[0];
    const float* mask = (const float*)d_in[1];
    const float* nw   = (const float*)d_in[2];
    const float* nb   = (const float*)d_in[3];
    const float* wl   = (const float*)d_in[4];
    const float* bl   = (const float*)d_in[5];
    const float* wr   = (const float*)d_in[6];
    const float* br   = (const float*)d_in[7];
    const float* wo   = (const float*)d_in[8];
    const float* bo   = (const float*)d_in[9];
    float* out = (float*)d_out;

    cudaFuncSetAttribute(pair_kernel, cudaFuncAttributeMaxDynamicSharedMemorySize, SMEM_PAIR);

    ln_proj_kernel<<<L, 256>>>(act, mask, nw, nb, wl, bl, wr, br);
    pair_kernel<<<L, 256, SMEM_PAIR>>>(wo, bo, out);
}

// round 10
// speedup vs baseline: 1.8085x; 1.0075x over previous
#include <cuda_runtime.h>
#include <cuda_fp16.h>
#include <cstdint>

// Problem constants (B=1)
#define L 768
#define C_IN 384
#define D 32          // C_OUTER
#define E 128         // C_OUT
#define EPS 1e-5f

// ---------------- scratch (no allocations allowed) ----------------
__device__ float g_right[L * D];
__device__ __align__(16) __half g_lh[L * D];   // left (fp16)

// ================= PTX helpers =================
__device__ __forceinline__ uint32_t smem_u32(const void* p) {
    uint32_t a;
    asm("{ .reg .u64 t; cvta.to.shared.u64 t, %1; cvt.u32.u64 %0, t; }" : "=r"(a) : "l"(p));
    return a;
}
__device__ __forceinline__ void ldsm_x4(uint32_t* r, uint32_t addr) {
    asm volatile("ldmatrix.sync.aligned.m8n8.x4.shared.b16 {%0,%1,%2,%3}, [%4];"
                 : "=r"(r[0]), "=r"(r[1]), "=r"(r[2]), "=r"(r[3]) : "r"(addr));
}
__device__ __forceinline__ void mma16816(float* c, const uint32_t* a, const uint32_t* b) {
    asm volatile("mma.sync.aligned.m16n8k16.row.col.f32.f16.f16.f32 "
                 "{%0,%1,%2,%3}, {%4,%5,%6,%7}, {%8,%9}, {%0,%1,%2,%3};"
                 : "+f"(c[0]), "+f"(c[1]), "+f"(c[2]), "+f"(c[3])
                 : "r"(a[0]), "r"(a[1]), "r"(a[2]), "r"(a[3]), "r"(b[0]), "r"(b[1]));
}
#define CP_ASYNC16(dst, src) \
    asm volatile("cp.async.ca.shared.global [%0], [%1], 16;" :: "r"(dst), "l"(src) : "memory")
#define CP_COMMIT()  asm volatile("cp.async.commit_group;" ::: "memory")
#define CP_WAIT0()   asm volatile("cp.async.wait_group 0;" ::: "memory")

// ---------------- Kernel A: LayerNorm + left/right projections ----------------
__global__ void __launch_bounds__(256) ln_proj_kernel(
    const float* __restrict__ act, const float* __restrict__ mask,
    const float* __restrict__ nw, const float* __restrict__ nb,
    const float* __restrict__ wl, const float* __restrict__ bl,
    const float* __restrict__ wr, const float* __restrict__ br)
{
    __shared__ float s_norm[C_IN];
    __shared__ float warp_sum[8];
    __shared__ float bcast;
    __shared__ float red[256];

    const int l = blockIdx.x;
    const int tid = threadIdx.x;
    const int lane = tid & 31;
    const int wid = tid >> 5;
    const float* arow = act + (size_t)l * C_IN;

    const float x0 = arow[tid];
    const float x1 = (tid < C_IN - 256) ? arow[256 + tid] : 0.0f;

    float s = x0 + x1;
    #pragma unroll
    for (int o = 16; o > 0; o >>= 1) s += __shfl_xor_sync(0xffffffffu, s, o);
    if (lane == 0) warp_sum[wid] = s;
    __syncthreads();
    if (tid == 0) {
        float t = 0.f;
        #pragma unroll
        for (int w = 0; w < 8; ++w) t += warp_sum[w];
        bcast = t * (1.0f / C_IN);
    }
    __syncthreads();
    const float mu = bcast;

    const float d0 = x0 - mu;
    const float d1 = (tid < C_IN - 256) ? (x1 - mu) : 0.0f;
    float v = d0 * d0 + d1 * d1;
    #pragma unroll
    for (int o = 16; o > 0; o >>= 1) v += __shfl_xor_sync(0xffffffffu, v, o);
    if (lane == 0) warp_sum[wid] = v;
    __syncthreads();
    if (tid == 0) {
        float t = 0.f;
        #pragma unroll
        for (int w = 0; w < 8; ++w) t += warp_sum[w];
        bcast = rsqrtf(t * (1.0f / C_IN) + EPS);
    }
    __syncthreads();
    const float rstd = bcast;

    s_norm[tid] = d0 * rstd * nw[tid] + nb[tid];
    if (tid < C_IN - 256)
        s_norm[256 + tid] = d1 * rstd * nw[256 + tid] + nb[256 + tid];
    __syncthreads();

    const int oc  = tid & 63;
    const int q   = tid >> 6;
    const int col = oc & 31;
    const float* w = (oc < 32) ? wl : wr;
    float dot = 0.0f;
    const int c0 = q * (C_IN / 4);
    #pragma unroll 8
    for (int c = c0; c < c0 + C_IN / 4; ++c)
        dot += s_norm[c] * w[c * D + col];
    red[tid] = dot;
    __syncthreads();
    if (tid < 128) red[tid] += red[tid + 128];
    __syncthreads();
    if (tid < 64) {
        const float vv = red[tid] + red[tid + 64];
        const float m = mask[l];
        const float val = m * (vv + ((oc < 32) ? bl[col] : br[col]));
        if (oc < 32) g_lh[l * D + col] = __float2half_rn(val);
        else         g_right[l * D + col] = val;
    }
}

// ---------------- Kernel C: mma.sync batched GEMM (fp16, K=32) ----------------
// grid = (2 j-halves, L i), block = 256 (8 warps: 2 mw x 4 nq), 12 j-tiles of 32 rows
// Warp tile: 16 rows x 32 cols -> acc 16 regs -> 4 CTAs/SM (occ 50%)
// A[j,k] fp16 32 halfs/row, stride 80 B, double-buffered via cp.async
// B[e,k] fp16 -> per-warp 32-col fragments hoisted to registers
// out[i,j,e] = A.B + lin[i,e]   (direct st.global.v2 epilogue)
#define RSTRIDE 80
#define BTILEB  10240
#define ATILEB  2560           // 32 rows x 80 B
#define SOFF_LIN   0
#define SOFF_B     512
#define SOFF_A0    (512 + BTILEB)
#define SOFF_A1    (512 + BTILEB + ATILEB)
#define SMEM_PAIR  (512 + BTILEB + 2 * ATILEB)   // 15872

__global__ void __launch_bounds__(256, 4) pair_kernel(
    const float* __restrict__ wo, const float* __restrict__ bo,
    float* __restrict__ out)
{
    extern __shared__ char smem[];
    __shared__ float r_s[D];
    const uint32_t sb = smem_u32(smem);
    const uint32_t sB = sb + SOFF_B;
    float* lin_s = reinterpret_cast<float*>(smem + SOFF_LIN);

    const int tid = threadIdx.x;
    const int wid = tid >> 5;
    const int lane = tid & 31;
    const int mw = wid & 1;          // m position: rows mw*16 within 32-row tile
    const int nq = wid >> 1;         // e quadrant: cols nq*32
    const int i = blockIdx.y;
    const int jh = blockIdx.x;       // 0/1 j-half

    if (tid < D) r_s[tid] = g_right[i * D + tid];
    __syncthreads();

    // ---- build B tile in smem (threads 0..127) + lin ----
    if (tid < E) {
        const int e = tid;
        float acc = 0.0f;
        alignas(16) __half hi[D];
        #pragma unroll
        for (int d = 0; d < D; ++d) {
            const float w1 = wo[d * E + e];
            const float w2 = wo[(D + d) * E + e];
            const float rd = r_s[d];
            hi[d] = __float2half_rn(fmaf(rd, w1, w2));
            acc = fmaf(rd, w2, acc);
        }
        lin_s[e] = bo[e] - acc;
        const uint4* h4 = reinterpret_cast<const uint4*>(hi);
        char* rowp = smem + SOFF_B + e * RSTRIDE;
        #pragma unroll
        for (int c = 0; c < 4; ++c)
            *reinterpret_cast<uint4*>(rowp + c * 16) = h4[c];
    }

    // ---- first A tile (32 rows) via cp.async into buffer 0 ----
    const __half* gA = g_lh;
    const int jbase = jh * 384;
    if (tid < 128) {
        const int row = tid >> 2, c = tid & 3;
        CP_ASYNC16(sb + SOFF_A0 + row * RSTRIDE + c * 16,
                   (const char*)(gA + (jbase + row) * D) + c * 16);
    }
    CP_COMMIT();
    CP_WAIT0();
    __syncthreads();

    // ---- hoist B fragments (32 cols per warp, both k-tiles) ----
    uint32_t bfr[2][4][2];
    #pragma unroll
    for (int kt = 0; kt < 2; ++kt) {
        #pragma unroll
        for (int p = 0; p < 2; ++p) {
            const uint32_t er = nq * 32 + p * 16;
            const uint32_t row = er + (lane & 7) + ((lane >> 4) << 3);
            const uint32_t addr = sB + row * RSTRIDE + kt * 32 + (((lane >> 3) & 1) << 4);
            uint32_t r[4];
            ldsm_x4(r, addr);
            bfr[kt][2 * p][0] = r[0]; bfr[kt][2 * p][1] = r[1];
            bfr[kt][2 * p + 1][0] = r[2]; bfr[kt][2 * p + 1][1] = r[3];
        }
    }

    // per-lane lin pair for each n
    float2 lreg[4];
    #pragma unroll
    for (int n = 0; n < 4; ++n)
        lreg[n] = reinterpret_cast<const float2*>(lin_s)[nq * 16 + n * 4 + (lane & 3)];

    for (int jt = 0; jt < 12; ++jt) {
        const int j0 = jbase + jt * 32;
        const uint32_t sA = sb + ((jt & 1) ? SOFF_A1 : SOFF_A0);
        const uint32_t sAnext = sb + ((jt & 1) ? SOFF_A0 : SOFF_A1);

        // ---- mainloop: 2 k-tiles of 16 ----
        float acc[4][4];
        #pragma unroll
        for (int n = 0; n < 4; ++n)
            #pragma unroll
            for (int q = 0; q < 4; ++q) acc[n][q] = 0.0f;

        #pragma unroll
        for (int kt = 0; kt < 2; ++kt) {
            const uint32_t jr = mw * 16 + (lane & 15);
            const uint32_t addr = sA + jr * RSTRIDE + kt * 32 + ((lane >> 4) << 4);
            uint32_t a[4];
            ldsm_x4(a, addr);
            #pragma unroll
            for (int n = 0; n < 4; ++n)
                mma16816(acc[n], a, bfr[kt][n]);
        }

        // ---- prefetch next A tile via cp.async ----
        const bool has_next = (jt < 11);
        if (has_next && tid < 128) {
            const int j1 = j0 + 32;
            const int row = tid >> 2, c = tid & 3;
            CP_ASYNC16(sAnext + row * RSTRIDE + c * 16,
                       (const char*)(gA + (j1 + row) * D) + c * 16);
        }
        if (has_next) CP_COMMIT();

        // ---- direct STG.64 epilogue ----
        const int r0 = mw * 16 + (lane >> 2);
        float* base0 = out + ((size_t)i * L + j0 + r0) * E + nq * 32 + 2 * (lane & 3);
        float* base1 = base0 + 8 * E;
        #pragma unroll
        for (int n = 0; n < 4; ++n) {
            float2 v0, v1;
            v0.x = acc[n][0] + lreg[n].x;  v0.y = acc[n][1] + lreg[n].y;
            v1.x = acc[n][2] + lreg[n].x;  v1.y = acc[n][3] + lreg[n].y;
            *reinterpret_cast<float2*>(base0 + n * 8) = v0;
            *reinterpret_cast<float2*>(base1 + n * 8) = v1;
        }

        if (has_next) {
            CP_WAIT0();
            __syncthreads();
        }
    }
}

// ---------------- launch ----------------
extern "C" void kernel_launch(void* const* d_in, const int* in_sizes, int n_in,
                              void* d_out, int out_size)
{
    const float* act  = (const float*)d_in[0];
    const float* mask = (const float*)d_in[1];
    const float* nw   = (const float*)d_in[2];
    const float* nb   = (const float*)d_in[3];
    const float* wl   = (const float*)d_in[4];
    const float* bl   = (const float*)d_in[5];
    const float* wr   = (const float*)d_in[6];
    const float* br   = (const float*)d_in[7];
    const float* wo   = (const float*)d_in[8];
    const float* bo   = (const float*)d_in[9];
    float* out = (float*)d_out;

    cudaFuncSetAttribute(pair_kernel, cudaFuncAttributeMaxDynamicSharedMemorySize, SMEM_PAIR);

    ln_proj_kernel<<<L, 256>>>(act, mask, nw, nb, wl, bl, wr, br);
    pair_kernel<<<dim3(2, L), 256, SMEM_PAIR>>>(wo, bo, out);
}

// round 11
// speedup vs baseline: 1.8844x; 1.0420x over previous
#include <cuda_runtime.h>
#include <cuda_fp16.h>
#include <cstdint>

// Problem constants (B=1)
#define L 768
#define C_IN 384
#define D 32          // C_OUTER
#define E 128         // C_OUT
#define EPS 1e-5f

// ---------------- scratch (no allocations allowed) ----------------
__device__ float g_right[L * D];
__device__ __align__(16) __half g_lh[L * D];   // left (fp16)

// ================= PTX helpers =================
__device__ __forceinline__ uint32_t smem_u32(const void* p) {
    uint32_t a;
    asm("{ .reg .u64 t; cvta.to.shared.u64 t, %1; cvt.u32.u64 %0, t; }" : "=r"(a) : "l"(p));
    return a;
}
__device__ __forceinline__ void ldsm_x4(uint32_t* r, uint32_t addr) {
    asm volatile("ldmatrix.sync.aligned.m8n8.x4.shared.b16 {%0,%1,%2,%3}, [%4];"
                 : "=r"(r[0]), "=r"(r[1]), "=r"(r[2]), "=r"(r[3]) : "r"(addr));
}
__device__ __forceinline__ void mma16816(float* c, const uint32_t* a, const uint32_t* b) {
    asm volatile("mma.sync.aligned.m16n8k16.row.col.f32.f16.f16.f32 "
                 "{%0,%1,%2,%3}, {%4,%5,%6,%7}, {%8,%9}, {%0,%1,%2,%3};"
                 : "+f"(c[0]), "+f"(c[1]), "+f"(c[2]), "+f"(c[3])
                 : "r"(a[0]), "r"(a[1]), "r"(a[2]), "r"(a[3]), "r"(b[0]), "r"(b[1]));
}
#define CP_ASYNC16(dst, src) \
    asm volatile("cp.async.ca.shared.global [%0], [%1], 16;" :: "r"(dst), "l"(src) : "memory")
#define CP_COMMIT()  asm volatile("cp.async.commit_group;" ::: "memory")
#define CP_WAIT0()   asm volatile("cp.async.wait_group 0;" ::: "memory")

// ---------------- Kernel A: LayerNorm + left/right projections ----------------
__global__ void __launch_bounds__(256) ln_proj_kernel(
    const float* __restrict__ act, const float* __restrict__ mask,
    const float* __restrict__ nw, const float* __restrict__ nb,
    const float* __restrict__ wl, const float* __restrict__ bl,
    const float* __restrict__ wr, const float* __restrict__ br)
{
    __shared__ float s_norm[C_IN];
    __shared__ float warp_sum[8];
    __shared__ float bcast;
    __shared__ float red[256];

    const int l = blockIdx.x;
    const int tid = threadIdx.x;
    const int lane = tid & 31;
    const int wid = tid >> 5;
    const float* arow = act + (size_t)l * C_IN;

    const float x0 = arow[tid];
    const float x1 = (tid < C_IN - 256) ? arow[256 + tid] : 0.0f;

    float s = x0 + x1;
    #pragma unroll
    for (int o = 16; o > 0; o >>= 1) s += __shfl_xor_sync(0xffffffffu, s, o);
    if (lane == 0) warp_sum[wid] = s;
    __syncthreads();
    if (tid == 0) {
        float t = 0.f;
        #pragma unroll
        for (int w = 0; w < 8; ++w) t += warp_sum[w];
        bcast = t * (1.0f / C_IN);
    }
    __syncthreads();
    const float mu = bcast;

    const float d0 = x0 - mu;
    const float d1 = (tid < C_IN - 256) ? (x1 - mu) : 0.0f;
    float v = d0 * d0 + d1 * d1;
    #pragma unroll
    for (int o = 16; o > 0; o >>= 1) v += __shfl_xor_sync(0xffffffffu, v, o);
    if (lane == 0) warp_sum[wid] = v;
    __syncthreads();
    if (tid == 0) {
        float t = 0.f;
        #pragma unroll
        for (int w = 0; w < 8; ++w) t += warp_sum[w];
        bcast = rsqrtf(t * (1.0f / C_IN) + EPS);
    }
    __syncthreads();
    const float rstd = bcast;

    s_norm[tid] = d0 * rstd * nw[tid] + nb[tid];
    if (tid < C_IN - 256)
        s_norm[256 + tid] = d1 * rstd * nw[256 + tid] + nb[256 + tid];
    __syncthreads();

    const int oc  = tid & 63;
    const int q   = tid >> 6;
    const int col = oc & 31;
    const float* w = (oc < 32) ? wl : wr;
    float dot = 0.0f;
    const int c0 = q * (C_IN / 4);
    #pragma unroll 8
    for (int c = c0; c < c0 + C_IN / 4; ++c)
        dot += s_norm[c] * w[c * D + col];
    red[tid] = dot;
    __syncthreads();
    if (tid < 128) red[tid] += red[tid + 128];
    __syncthreads();
    if (tid < 64) {
        const float vv = red[tid] + red[tid + 64];
        const float m = mask[l];
        const float val = m * (vv + ((oc < 32) ? bl[col] : br[col]));
        if (oc < 32) g_lh[l * D + col] = __float2half_rn(val);
        else         g_right[l * D + col] = val;
    }
}

// ---------------- Kernel C: mma.sync batched GEMM (fp16, K=32) ----------------
// grid = (2 j-halves, L i), block = 256 (8 warps: 2 mw x 4 nq), 12 j-tiles of 32 rows
// A double-buffered via cp.async; B fragments hoisted; output staged through
// swizzled smem so every STG.128 writes one full 512B row (4 full lines).
#define RSTRIDE 80
#define BTILEB  10240
#define ATILEB  2560           // 32 rows x 80 B
#define SOFF_LIN   0
#define SOFF_B     512
#define SOFF_A0    (512 + BTILEB)
#define SOFF_A1    (512 + BTILEB + ATILEB)
#define SOFF_STG   (512 + BTILEB + 2 * ATILEB)       // 15872
#define SMEM_PAIR  (SOFF_STG + 32 * 512)             // 32256

__global__ void __launch_bounds__(256, 4) pair_kernel(
    const float* __restrict__ wo, const float* __restrict__ bo,
    float* __restrict__ out)
{
    extern __shared__ char smem[];
    __shared__ float r_s[D];
    const uint32_t sb = smem_u32(smem);
    const uint32_t sB = sb + SOFF_B;
    const uint32_t sStage = sb + SOFF_STG;
    float* lin_s = reinterpret_cast<float*>(smem + SOFF_LIN);

    const int tid = threadIdx.x;
    const int wid = tid >> 5;
    const int lane = tid & 31;
    const int mw = wid & 1;          // m position: rows mw*16 within 32-row tile
    const int nq = wid >> 1;         // e quadrant: cols nq*32
    const int i = blockIdx.y;
    const int jh = blockIdx.x;       // 0/1 j-half

    if (tid < D) r_s[tid] = g_right[i * D + tid];
    __syncthreads();

    // ---- build B tile in smem (threads 0..127) + lin ----
    if (tid < E) {
        const int e = tid;
        float acc = 0.0f;
        alignas(16) __half hi[D];
        #pragma unroll
        for (int d = 0; d < D; ++d) {
            const float w1 = wo[d * E + e];
            const float w2 = wo[(D + d) * E + e];
            const float rd = r_s[d];
            hi[d] = __float2half_rn(fmaf(rd, w1, w2));
            acc = fmaf(rd, w2, acc);
        }
        lin_s[e] = bo[e] - acc;
        const uint4* h4 = reinterpret_cast<const uint4*>(hi);
        char* rowp = smem + SOFF_B + e * RSTRIDE;
        #pragma unroll
        for (int c = 0; c < 4; ++c)
            *reinterpret_cast<uint4*>(rowp + c * 16) = h4[c];
    }

    // ---- first A tile (32 rows) via cp.async into buffer 0 ----
    const __half* gA = g_lh;
    const int jbase = jh * 384;
    if (tid < 128) {
        const int row = tid >> 2, c = tid & 3;
        CP_ASYNC16(sb + SOFF_A0 + row * RSTRIDE + c * 16,
                   (const char*)(gA + (jbase + row) * D) + c * 16);
    }
    CP_COMMIT();
    CP_WAIT0();
    __syncthreads();

    // ---- hoist B fragments (32 cols per warp, both k-tiles) ----
    uint32_t bfr[2][4][2];
    #pragma unroll
    for (int kt = 0; kt < 2; ++kt) {
        #pragma unroll
        for (int p = 0; p < 2; ++p) {
            const uint32_t er = nq * 32 + p * 16;
            const uint32_t row = er + (lane & 7) + ((lane >> 4) << 3);
            const uint32_t addr = sB + row * RSTRIDE + kt * 32 + (((lane >> 3) & 1) << 4);
            uint32_t r[4];
            ldsm_x4(r, addr);
            bfr[kt][2 * p][0] = r[0]; bfr[kt][2 * p][1] = r[1];
            bfr[kt][2 * p + 1][0] = r[2]; bfr[kt][2 * p + 1][1] = r[3];
        }
    }

    // per-lane lin float4 (cols lane*4..lane*4+3, for STG phase)
    const float4 lreg = reinterpret_cast<const float4*>(lin_s)[lane];

    for (int jt = 0; jt < 12; ++jt) {
        const int j0 = jbase + jt * 32;
        const uint32_t sA = sb + ((jt & 1) ? SOFF_A1 : SOFF_A0);
        const uint32_t sAnext = sb + ((jt & 1) ? SOFF_A0 : SOFF_A1);

        // ---- mainloop: 2 k-tiles of 16 ----
        float acc[4][4];
        #pragma unroll
        for (int n = 0; n < 4; ++n)
            #pragma unroll
            for (int q = 0; q < 4; ++q) acc[n][q] = 0.0f;

        #pragma unroll
        for (int kt = 0; kt < 2; ++kt) {
            const uint32_t jr = mw * 16 + (lane & 15);
            const uint32_t addr = sA + jr * RSTRIDE + kt * 32 + ((lane >> 4) << 4);
            uint32_t a[4];
            ldsm_x4(a, addr);
            #pragma unroll
            for (int n = 0; n < 4; ++n)
                mma16816(acc[n], a, bfr[kt][n]);
        }

        // ---- prefetch next A tile (safe: targets the other buffer) ----
        const bool has_next = (jt < 11);
        if (has_next && tid < 128) {
            const int j1 = j0 + 32;
            const int row = tid >> 2, c = tid & 3;
            CP_ASYNC16(sAnext + row * RSTRIDE + c * 16,
                       (const char*)(gA + (j1 + row) * D) + c * 16);
        }
        if (has_next) CP_COMMIT();

        // ---- STS raw acc into swizzled stage (conflict-free) ----
        #pragma unroll
        for (int h = 0; h < 2; ++h) {
            const uint32_t r = mw * 16 + (lane >> 2) + 8 * h;
            const uint32_t rbase = sStage + r * 512 + ((lane & 1) << 3);
            const uint32_t sw = (r & 7) << 1;
            #pragma unroll
            for (int n = 0; n < 4; ++n) {
                const uint32_t chunk = nq * 8 + n * 2 + ((lane & 3) >> 1);
                const uint32_t addr = rbase + ((chunk ^ sw) << 4);
                asm volatile("st.shared.v2.f32 [%0], {%1,%2};"
                             :: "r"(addr), "f"(acc[n][2 * h]), "f"(acc[n][2 * h + 1]) : "memory");
            }
        }
        __syncthreads();

        // ---- drain: each warp owns 4 rows; one STG.128 writes a full 512B row ----
        #pragma unroll
        for (int rr = 0; rr < 4; ++rr) {
            const uint32_t r2 = wid * 4 + rr;
            const uint32_t la = sStage + r2 * 512 + (((uint32_t)lane ^ ((r2 & 7) << 1)) << 4);
            float v0, v1, v2, v3;
            asm volatile("ld.shared.v4.f32 {%0,%1,%2,%3}, [%4];"
                         : "=f"(v0), "=f"(v1), "=f"(v2), "=f"(v3) : "r"(la));
            float4 v;
            v.x = v0 + lreg.x; v.y = v1 + lreg.y; v.z = v2 + lreg.z; v.w = v3 + lreg.w;
            *reinterpret_cast<float4*>(out + ((size_t)i * L + j0 + r2) * E + lane * 4) = v;
        }

        if (has_next) CP_WAIT0();
        __syncthreads();
    }
}

// ---------------- launch ----------------
extern "C" void kernel_launch(void* const* d_in, const int* in_sizes, int n_in,
                              void* d_out, int out_size)
{
    const float* act  = (const float*)d_in[0];
    const float* mask = (const float*)d_in[1];
    const float* nw   = (const float*)d_in[2];
    const float* nb   = (const float*)d_in[3];
    const float* wl   = (const float*)d_in[4];
    const float* bl   = (const float*)d_in[5];
    const float* wr   = (const float*)d_in[6];
    const float* br   = (const float*)d_in[7];
    const float* wo   = (const float*)d_in[8];
    const float* bo   = (const float*)d_in[9];
    float* out = (float*)d_out;

    cudaFuncSetAttribute(pair_kernel, cudaFuncAttributeMaxDynamicSharedMemorySize, SMEM_PAIR);

    ln_proj_kernel<<<L, 256>>>(act, mask, nw, nb, wl, bl, wr, br);
    pair_kernel<<<dim3(2, L), 256, SMEM_PAIR>>>(wo, bo, out);
}